// round 1
// baseline (speedup 1.0000x reference)
#include <cuda_runtime.h>

#define TSEQ   2048
#define BATCH  4
#define NHEAD  16
#define HD     128
#define DIM    2048
#define MROWS  (BATCH * TSEQ)   // 8192
#define KVDIM  (2 * DIM)        // 4096

// ---------------- scratch (allocation-free: __device__ globals) ----------------
__device__ float g_kv[(size_t)MROWS * KVDIM];  // [B*T, 4096]  (k | v)
__device__ float g_q [(size_t)MROWS * DIM];    // [B*T, 2048]
__device__ float g_ao[(size_t)MROWS * DIM];    // attention output, [B*T, 2048]

// ---------------- GEMM: C[M,N] = A[M,K] @ B[K,N] + bias[N] ----------------
// 128x128 tile, BK=8, 256 threads, 8x8 per thread. All dims divisible.
__global__ __launch_bounds__(256) void gemm_bias_kernel(
    const float* __restrict__ A, const float* __restrict__ B,
    const float* __restrict__ bias, float* __restrict__ C,
    int M, int N, int K)
{
    __shared__ float As[8][128];   // transposed: As[k][m]
    __shared__ float Bs[8][128];

    const int tid = threadIdx.x;
    const int bm = blockIdx.y * 128;
    const int bn = blockIdx.x * 128;
    const int tm = (tid >> 4) * 8;
    const int tn = (tid & 15) * 8;

    float acc[8][8];
#pragma unroll
    for (int i = 0; i < 8; i++)
#pragma unroll
        for (int j = 0; j < 8; j++) acc[i][j] = 0.f;

    const int a_r = tid >> 1;          // 0..127
    const int a_c = (tid & 1) * 4;     // 0 or 4
    const int b_r = tid >> 5;          // 0..7
    const int b_c = (tid & 31) * 4;    // 0..124

    const float* Aptr = A + (size_t)(bm + a_r) * K + a_c;
    const float* Bptr = B + (size_t)b_r * N + bn + b_c;

    for (int k0 = 0; k0 < K; k0 += 8) {
        float4 av = *(const float4*)(Aptr + k0);
        float4 bv = *(const float4*)(Bptr + (size_t)k0 * N);
        As[a_c + 0][a_r] = av.x;
        As[a_c + 1][a_r] = av.y;
        As[a_c + 2][a_r] = av.z;
        As[a_c + 3][a_r] = av.w;
        *(float4*)&Bs[b_r][b_c] = bv;
        __syncthreads();

#pragma unroll
        for (int k = 0; k < 8; k++) {
            float a[8], bb[8];
            *(float4*)&a[0]  = *(const float4*)&As[k][tm];
            *(float4*)&a[4]  = *(const float4*)&As[k][tm + 4];
            *(float4*)&bb[0] = *(const float4*)&Bs[k][tn];
            *(float4*)&bb[4] = *(const float4*)&Bs[k][tn + 4];
#pragma unroll
            for (int i = 0; i < 8; i++)
#pragma unroll
                for (int j = 0; j < 8; j++)
                    acc[i][j] += a[i] * bb[j];
        }
        __syncthreads();
    }

    float bb[8];
#pragma unroll
    for (int j = 0; j < 8; j++) bb[j] = bias[bn + tn + j];

#pragma unroll
    for (int i = 0; i < 8; i++) {
        float* crow = C + (size_t)(bm + tm + i) * N + bn + tn;
        float4 o0, o1;
        o0.x = acc[i][0] + bb[0]; o0.y = acc[i][1] + bb[1];
        o0.z = acc[i][2] + bb[2]; o0.w = acc[i][3] + bb[3];
        o1.x = acc[i][4] + bb[4]; o1.y = acc[i][5] + bb[5];
        o1.z = acc[i][6] + bb[6]; o1.w = acc[i][7] + bb[7];
        *(float4*)(crow)     = o0;
        *(float4*)(crow + 4) = o1;
    }
}

// ---------------- Flash attention (causal, fp32, online softmax) ----------------
// Block: 64 query rows x full head dim 128. 256 threads.
// Score stage: thread grid 16x16, each 4 rows x 4 cols of the 64x64 S tile.
// PV stage:    same rows, 8 output cols each (16x8 = 128).
struct __align__(16) AttnSmem {
    float sQ [64][132];   // padded stride 132: conflict-free, float4-aligned
    float sKT[128][68];   // K transposed: [d][key], padded
    float sV [64][128];
    float sP [64][68];    // padded for float4 + bank spread
    float sRed[64][16];
    float m_sh[64];
    float l_sh[64];
    float alpha_sh[64];
};

__global__ __launch_bounds__(256) void attn_kernel(
    const float* __restrict__ qbuf, const float* __restrict__ kvbuf,
    float* __restrict__ aobuf)
{
    extern __shared__ char smem_raw[];
    AttnSmem& s = *reinterpret_cast<AttnSmem*>(smem_raw);

    const int tid   = threadIdx.x;
    const int qtile = blockIdx.x;          // 0..31
    const int bh    = blockIdx.y;          // 0..63
    const int b     = bh >> 4;
    const int h     = bh & 15;
    const int q0    = qtile * 64;
    const float scale = 0.08838834764831845f;  // 1/sqrt(128)

    const float* qbase = qbuf  + (size_t)b * TSEQ * DIM   + (size_t)h * HD;
    const float* kbase = kvbuf + (size_t)b * TSEQ * KVDIM + (size_t)h * HD;
    const float* vbase = kbase + DIM;
    float*       obase = aobuf + (size_t)b * TSEQ * DIM   + (size_t)h * HD;

    // load Q tile (pre-scaled)
#pragma unroll
    for (int it = 0; it < 8; it++) {
        int i  = tid + it * 256;      // 0..2047  (64 rows x 32 float4)
        int r  = i >> 5;
        int c4 = (i & 31) << 2;
        float4 v = *(const float4*)(qbase + (size_t)(q0 + r) * DIM + c4);
        s.sQ[r][c4 + 0] = v.x * scale;
        s.sQ[r][c4 + 1] = v.y * scale;
        s.sQ[r][c4 + 2] = v.z * scale;
        s.sQ[r][c4 + 3] = v.w * scale;
    }
    if (tid < 64) { s.m_sh[tid] = -1e30f; s.l_sh[tid] = 0.f; }

    const int ty  = tid >> 4;
    const int tx  = tid & 15;
    const int r0  = ty * 4;
    const int c0s = tx * 4;
    const int c0o = tx * 8;

    float oacc[4][8];
#pragma unroll
    for (int i = 0; i < 4; i++)
#pragma unroll
        for (int j = 0; j < 8; j++) oacc[i][j] = 0.f;

    for (int j = 0; j <= qtile; j++) {
        const int j0 = j * 64;
        __syncthreads();  // prev PV / l-update done before overwriting K/V

        // load K (transposed into sKT) and V
#pragma unroll
        for (int it = 0; it < 8; it++) {
            int i  = tid + it * 256;
            int r  = i >> 5;
            int c4 = (i & 31) << 2;
            float4 k4 = *(const float4*)(kbase + (size_t)(j0 + r) * KVDIM + c4);
            s.sKT[c4 + 0][r] = k4.x;
            s.sKT[c4 + 1][r] = k4.y;
            s.sKT[c4 + 2][r] = k4.z;
            s.sKT[c4 + 3][r] = k4.w;
            float4 v4 = *(const float4*)(vbase + (size_t)(j0 + r) * KVDIM + c4);
            *(float4*)&s.sV[r][c4] = v4;
        }
        __syncthreads();

        // S = Q K^T (Q already scaled)
        float acc[4][4];
#pragma unroll
        for (int i = 0; i < 4; i++)
#pragma unroll
            for (int c = 0; c < 4; c++) acc[i][c] = 0.f;

#pragma unroll 2
        for (int d4 = 0; d4 < HD; d4 += 4) {
            float qreg[4][4];
#pragma unroll
            for (int rr = 0; rr < 4; rr++)
                *(float4*)&qreg[rr][0] = *(const float4*)&s.sQ[r0 + rr][d4];
#pragma unroll
            for (int dd = 0; dd < 4; dd++) {
                float4 kv = *(const float4*)&s.sKT[d4 + dd][c0s];
                float kr[4] = {kv.x, kv.y, kv.z, kv.w};
#pragma unroll
                for (int rr = 0; rr < 4; rr++)
#pragma unroll
                    for (int cc = 0; cc < 4; cc++)
                        acc[rr][cc] += qreg[rr][dd] * kr[cc];
            }
        }

        // causal mask on diagonal tile
        if (j == qtile) {
#pragma unroll
            for (int rr = 0; rr < 4; rr++)
#pragma unroll
                for (int cc = 0; cc < 4; cc++)
                    if (j0 + c0s + cc > q0 + r0 + rr) acc[rr][cc] = -1e30f;
        }

        // row-max partial
#pragma unroll
        for (int rr = 0; rr < 4; rr++) {
            float tm0 = fmaxf(fmaxf(acc[rr][0], acc[rr][1]),
                              fmaxf(acc[rr][2], acc[rr][3]));
            s.sRed[r0 + rr][tx] = tm0;
        }
        __syncthreads();
        if (tid < 64) {
            float mx = s.sRed[tid][0];
#pragma unroll
            for (int t = 1; t < 16; t++) mx = fmaxf(mx, s.sRed[tid][t]);
            float mo = s.m_sh[tid];
            float mn = fmaxf(mo, mx);
            s.alpha_sh[tid] = __expf(mo - mn);
            s.m_sh[tid]     = mn;
        }
        __syncthreads();

        // P = exp(S - m), partial row sums, write P; rescale O
#pragma unroll
        for (int rr = 0; rr < 4; rr++) {
            float mrow = s.m_sh[r0 + rr];
            float ps = 0.f;
#pragma unroll
            for (int cc = 0; cc < 4; cc++) {
                float p = __expf(acc[rr][cc] - mrow);
                ps += p;
                s.sP[r0 + rr][c0s + cc] = p;
            }
            s.sRed[r0 + rr][tx] = ps;
        }
#pragma unroll
        for (int rr = 0; rr < 4; rr++) {
            float a = s.alpha_sh[r0 + rr];
#pragma unroll
            for (int c = 0; c < 8; c++) oacc[rr][c] *= a;
        }
        __syncthreads();
        if (tid < 64) {
            float sm = 0.f;
#pragma unroll
            for (int t = 0; t < 16; t++) sm += s.sRed[tid][t];
            s.l_sh[tid] = s.l_sh[tid] * s.alpha_sh[tid] + sm;
        }

        // O += P @ V
#pragma unroll 2
        for (int k4 = 0; k4 < 64; k4 += 4) {
            float preg[4][4];
#pragma unroll
            for (int rr = 0; rr < 4; rr++)
                *(float4*)&preg[rr][0] = *(const float4*)&s.sP[r0 + rr][k4];
#pragma unroll
            for (int dd = 0; dd < 4; dd++) {
                int kk = k4 + dd;
                float4 v0 = *(const float4*)&s.sV[kk][c0o];
                float4 v1 = *(const float4*)&s.sV[kk][c0o + 4];
                float vr[8] = {v0.x, v0.y, v0.z, v0.w, v1.x, v1.y, v1.z, v1.w};
#pragma unroll
                for (int rr = 0; rr < 4; rr++)
#pragma unroll
                    for (int c = 0; c < 8; c++)
                        oacc[rr][c] += preg[rr][dd] * vr[c];
            }
        }
    }

    __syncthreads();
    // normalize + store
#pragma unroll
    for (int rr = 0; rr < 4; rr++) {
        int row = r0 + rr;
        float inv = 1.f / s.l_sh[row];
        float4 o0, o1;
        o0.x = oacc[rr][0] * inv; o0.y = oacc[rr][1] * inv;
        o0.z = oacc[rr][2] * inv; o0.w = oacc[rr][3] * inv;
        o1.x = oacc[rr][4] * inv; o1.y = oacc[rr][5] * inv;
        o1.z = oacc[rr][6] * inv; o1.w = oacc[rr][7] * inv;
        float* op = obase + (size_t)(q0 + row) * DIM + c0o;
        *(float4*)(op)     = o0;
        *(float4*)(op + 4) = o1;
    }
}

// ---------------- launch ----------------
extern "C" void kernel_launch(void* const* d_in, const int* in_sizes, int n_in,
                              void* d_out, int out_size)
{
    const float* enc  = (const float*)d_in[0];
    const float* dec  = (const float*)d_in[1];
    const float* W_kv = (const float*)d_in[2];
    const float* b_kv = (const float*)d_in[3];
    const float* W_q  = (const float*)d_in[4];
    const float* b_q  = (const float*)d_in[5];
    const float* W_o  = (const float*)d_in[6];
    const float* b_o  = (const float*)d_in[7];
    float* out = (float*)d_out;

    float *p_kv, *p_q, *p_ao;
    cudaGetSymbolAddress((void**)&p_kv, g_kv);
    cudaGetSymbolAddress((void**)&p_q,  g_q);
    cudaGetSymbolAddress((void**)&p_ao, g_ao);

    cudaFuncSetAttribute(attn_kernel,
                         cudaFuncAttributeMaxDynamicSharedMemorySize,
                         (int)sizeof(AttnSmem));

    // kv = enc @ W_kv + b_kv   (8192 x 4096 x 2048)
    gemm_bias_kernel<<<dim3(KVDIM / 128, MROWS / 128), 256>>>(
        enc, W_kv, b_kv, p_kv, MROWS, KVDIM, DIM);
    // q = dec @ W_q + b_q      (8192 x 2048 x 2048)
    gemm_bias_kernel<<<dim3(DIM / 128, MROWS / 128), 256>>>(
        dec, W_q, b_q, p_q, MROWS, DIM, DIM);
    // causal multi-head attention
    attn_kernel<<<dim3(TSEQ / 64, BATCH * NHEAD), 256, sizeof(AttnSmem)>>>(
        p_q, p_kv, p_ao);
    // out = ao @ W_o + b_o
    gemm_bias_kernel<<<dim3(DIM / 128, MROWS / 128), 256>>>(
        p_ao, W_o, b_o, out, MROWS, DIM, DIM);
}

// round 3
// speedup vs baseline: 1.6793x; 1.6793x over previous
#include <cuda_runtime.h>
#include <cuda_bf16.h>
#include <cstdint>

#define TSEQ   2048
#define BATCH  4
#define NHEAD  16
#define HD     128
#define DIM    2048
#define MROWS  (BATCH * TSEQ)   // 8192
#define KVDIM  (2 * DIM)        // 4096

// ---------------- scratch (allocation-free: __device__ globals) ----------------
__device__ float g_kv[(size_t)MROWS * KVDIM];
__device__ float g_q [(size_t)MROWS * DIM];
__device__ float g_ao[(size_t)MROWS * DIM];
__device__ __nv_bfloat16 g_Ah[(size_t)MROWS * DIM];   // activation hi
__device__ __nv_bfloat16 g_Al[(size_t)MROWS * DIM];   // activation lo
__device__ __nv_bfloat16 g_Wh[(size_t)KVDIM * DIM];   // weight hi, [N,K] layout
__device__ __nv_bfloat16 g_Wl[(size_t)KVDIM * DIM];   // weight lo, [N,K] layout

// ---------------- helpers ----------------
__device__ __forceinline__ uint32_t smem_u32(const void* p) {
    uint32_t a;
    asm("{ .reg .u64 t; cvta.to.shared.u64 t, %1; cvt.u32.u64 %0, t; }"
        : "=r"(a) : "l"(p));
    return a;
}

__device__ __forceinline__ void ldmatrix_x4(uint32_t* r, uint32_t addr) {
    asm volatile("ldmatrix.sync.aligned.m8n8.x4.shared.b16 {%0,%1,%2,%3}, [%4];"
                 : "=r"(r[0]), "=r"(r[1]), "=r"(r[2]), "=r"(r[3]) : "r"(addr));
}

__device__ __forceinline__ void mma_bf16(float* d, const uint32_t* a, const uint32_t* b) {
    asm volatile(
        "mma.sync.aligned.m16n8k16.row.col.f32.bf16.bf16.f32 "
        "{%0,%1,%2,%3}, {%4,%5,%6,%7}, {%8,%9}, {%0,%1,%2,%3};"
        : "+f"(d[0]), "+f"(d[1]), "+f"(d[2]), "+f"(d[3])
        : "r"(a[0]), "r"(a[1]), "r"(a[2]), "r"(a[3]), "r"(b[0]), "r"(b[1]));
}

// ---------------- conversion kernels ----------------
__global__ __launch_bounds__(256) void conv_split_kernel(
    const float* __restrict__ x, __nv_bfloat16* __restrict__ h,
    __nv_bfloat16* __restrict__ l, int n4)
{
    int i = blockIdx.x * 256 + threadIdx.x;
    if (i >= n4) return;
    float4 v = ((const float4*)x)[i];
    float a[4] = {v.x, v.y, v.z, v.w};
    __nv_bfloat16 hh[4], ll[4];
#pragma unroll
    for (int k = 0; k < 4; k++) {
        hh[k] = __float2bfloat16(a[k]);
        ll[k] = __float2bfloat16(a[k] - __bfloat162float(hh[k]));
    }
    __nv_bfloat162* hp = (__nv_bfloat162*)(h + (size_t)i * 4);
    __nv_bfloat162* lp = (__nv_bfloat162*)(l + (size_t)i * 4);
    hp[0] = __nv_bfloat162{hh[0], hh[1]};
    hp[1] = __nv_bfloat162{hh[2], hh[3]};
    lp[0] = __nv_bfloat162{ll[0], ll[1]};
    lp[1] = __nv_bfloat162{ll[2], ll[3]};
}

// fp32 W[K,N] -> (hi, lo) bf16 [N,K] (transpose)
__global__ __launch_bounds__(256) void conv_w_kernel(
    const float* __restrict__ W, __nv_bfloat16* __restrict__ Wh,
    __nv_bfloat16* __restrict__ Wl, int K, int N)
{
    __shared__ float t[32][33];
    int n0 = blockIdx.x * 32, k0 = blockIdx.y * 32;
    int tx = threadIdx.x, ty = threadIdx.y;   // 32 x 8
#pragma unroll
    for (int r = 0; r < 4; r++)
        t[ty + 8 * r][tx] = W[(size_t)(k0 + ty + 8 * r) * N + n0 + tx];
    __syncthreads();
#pragma unroll
    for (int r = 0; r < 4; r++) {
        float v = t[tx][ty + 8 * r];
        int n = n0 + ty + 8 * r;
        __nv_bfloat16 hh = __float2bfloat16(v);
        Wh[(size_t)n * K + k0 + tx] = hh;
        Wl[(size_t)n * K + k0 + tx] = __float2bfloat16(v - __bfloat162float(hh));
    }
}

// ---------------- mma.sync GEMM ----------------
// C[M,N] = sum over 3 passes of A_p[M,2048] @ B_p[N,2048]^T + bias
// CTA 128x128, BK=64, double buffered. 256 threads = 8 warps, warp tile 64x32.
// Smem rows: 72 bf16 (144 B) stride -> conflict-free ldmatrix + LDS.
#define BK       64
#define ASTRIDE  72                       // bf16 elements per smem row
#define ROWB     (ASTRIDE * 2)            // 144 bytes
#define ATILE_B  (128 * ROWB)             // 18432
#define BUF_B    (2 * ATILE_B)            // 36864 per buffer
#define GEMM_SMEM (2 * BUF_B)             // 73728
#define NCH 96                            // 3 passes * 32 K-chunks

__global__ __launch_bounds__(256) void gemm_tc_kernel(
    const __nv_bfloat16* __restrict__ Ah, const __nv_bfloat16* __restrict__ Al,
    const __nv_bfloat16* __restrict__ Bh, const __nv_bfloat16* __restrict__ Bl,
    const float* __restrict__ bias, float* __restrict__ C, int N)
{
    extern __shared__ char smem[];
    const uint32_t sbase = smem_u32(smem);
    const int tid  = threadIdx.x;
    const int wid  = tid >> 5;
    const int lane = tid & 31;
    const int wm   = wid & 1;        // 2 warps in M
    const int wn   = wid >> 1;       // 4 warps in N
    const int bm   = blockIdx.y * 128;
    const int bn   = blockIdx.x * 128;

    const __nv_bfloat16* APs[3] = {Ah, Al, Ah};
    const __nv_bfloat16* BPs[3] = {Bh, Bh, Bl};

    float acc[4][4][4];
#pragma unroll
    for (int i = 0; i < 4; i++)
#pragma unroll
        for (int j = 0; j < 4; j++)
#pragma unroll
            for (int k = 0; k < 4; k++) acc[i][j][k] = 0.f;

    // per-lane fragment offsets (bytes)
    const uint32_t a_lane_off = (uint32_t)((lane & 15) * ROWB + ((lane >> 4) << 3) * 2);
    const uint32_t b_lane_off = (uint32_t)((lane >> 2) * ROWB + (lane & 3) * 4);
    const uint32_t a_warp_base = (uint32_t)(wm * 64) * ROWB;
    const uint32_t b_warp_base = (uint32_t)(ATILE_B + (wn * 32) * ROWB);

    // chunk loader: 128x64 bf16 A tile + 128x64 bf16 B tile (16B cp.async each)
    auto load_chunk = [&](int ci, int buf) {
        const int pass = ci >> 5;
        const int k0 = (ci & 31) * BK;
        const __nv_bfloat16* Ap = APs[pass];
        const __nv_bfloat16* Bp = BPs[pass];
        const uint32_t base = sbase + (uint32_t)buf * BUF_B;
#pragma unroll
        for (int j = 0; j < 8; j++) {
            int c = j * 256 + tid;          // 0..2047
            int row = (c >> 3) & 127;
            int c16 = c & 7;
            uint32_t dst;
            const __nv_bfloat16* g;
            if (c < 1024) {
                dst = base + (uint32_t)(row * ROWB + c16 * 16);
                g = Ap + (size_t)(bm + row) * DIM + k0 + c16 * 8;
            } else {
                dst = base + (uint32_t)(ATILE_B + row * ROWB + c16 * 16);
                g = Bp + (size_t)(bn + row) * DIM + k0 + c16 * 8;
            }
            asm volatile("cp.async.cg.shared.global [%0], [%1], 16;" :: "r"(dst), "l"(g));
        }
        asm volatile("cp.async.commit_group;");
    };

    load_chunk(0, 0);

    for (int i = 0; i < NCH; i++) {
        const int b = i & 1;
        const bool has_next = (i + 1 < NCH);
        if (has_next) load_chunk(i + 1, b ^ 1);
        if (has_next) asm volatile("cp.async.wait_group 1;");
        else          asm volatile("cp.async.wait_group 0;");
        __syncthreads();

        const uint32_t abuf = sbase + (uint32_t)b * BUF_B;
#pragma unroll
        for (int ks = 0; ks < 4; ks++) {
            uint32_t afrag[4][4];
#pragma unroll
            for (int mf = 0; mf < 4; mf++)
                ldmatrix_x4(afrag[mf],
                            abuf + a_warp_base + (uint32_t)(mf * 16 * ROWB)
                                 + (uint32_t)(ks * 32) + a_lane_off);
            uint32_t bfrag[4][2];
#pragma unroll
            for (int nf = 0; nf < 4; nf++) {
                uint32_t boff = (uint32_t)b * BUF_B + b_warp_base
                              + (uint32_t)(nf * 8 * ROWB) + (uint32_t)(ks * 32) + b_lane_off;
                bfrag[nf][0] = *(const uint32_t*)(smem + boff);
                bfrag[nf][1] = *(const uint32_t*)(smem + boff + 16);
            }
#pragma unroll
            for (int mf = 0; mf < 4; mf++)
#pragma unroll
                for (int nf = 0; nf < 4; nf++)
                    mma_bf16(acc[mf][nf], afrag[mf], bfrag[nf]);
        }
        __syncthreads();
    }

    // epilogue: bias + store
    float2 bfr[4];
#pragma unroll
    for (int nf = 0; nf < 4; nf++) {
        int col = bn + wn * 32 + nf * 8 + (lane & 3) * 2;
        bfr[nf].x = __ldg(bias + col);
        bfr[nf].y = __ldg(bias + col + 1);
    }
#pragma unroll
    for (int mf = 0; mf < 4; mf++) {
#pragma unroll
        for (int h = 0; h < 2; h++) {
            int row = bm + wm * 64 + mf * 16 + (lane >> 2) + h * 8;
            float* crow = C + (size_t)row * N + bn + wn * 32;
#pragma unroll
            for (int nf = 0; nf < 4; nf++) {
                float2 v;
                v.x = acc[mf][nf][2 * h + 0] + bfr[nf].x;
                v.y = acc[mf][nf][2 * h + 1] + bfr[nf].y;
                *(float2*)(crow + nf * 8 + (lane & 3) * 2) = v;
            }
        }
    }
}

// ---------------- Flash attention (causal, fp32, online softmax) ----------------
struct __align__(16) AttnSmem {
    float sQ [64][132];
    float sKT[128][68];
    float sV [64][128];
    float sP [64][68];
    float sRed[64][16];
    float m_sh[64];
    float l_sh[64];
    float alpha_sh[64];
};

__global__ __launch_bounds__(256) void attn_kernel(
    const float* __restrict__ qbuf, const float* __restrict__ kvbuf,
    float* __restrict__ aobuf)
{
    extern __shared__ char smem_raw[];
    AttnSmem& s = *reinterpret_cast<AttnSmem*>(smem_raw);

    const int tid   = threadIdx.x;
    const int qtile = blockIdx.x;
    const int bh    = blockIdx.y;
    const int b     = bh >> 4;
    const int h     = bh & 15;
    const int q0    = qtile * 64;
    const float scale = 0.08838834764831845f;

    const float* qbase = qbuf  + (size_t)b * TSEQ * DIM   + (size_t)h * HD;
    const float* kbase = kvbuf + (size_t)b * TSEQ * KVDIM + (size_t)h * HD;
    const float* vbase = kbase + DIM;
    float*       obase = aobuf + (size_t)b * TSEQ * DIM   + (size_t)h * HD;

#pragma unroll
    for (int it = 0; it < 8; it++) {
        int i  = tid + it * 256;
        int r  = i >> 5;
        int c4 = (i & 31) << 2;
        float4 v = *(const float4*)(qbase + (size_t)(q0 + r) * DIM + c4);
        s.sQ[r][c4 + 0] = v.x * scale;
        s.sQ[r][c4 + 1] = v.y * scale;
        s.sQ[r][c4 + 2] = v.z * scale;
        s.sQ[r][c4 + 3] = v.w * scale;
    }
    if (tid < 64) { s.m_sh[tid] = -1e30f; s.l_sh[tid] = 0.f; }

    const int ty  = tid >> 4;
    const int tx  = tid & 15;
    const int r0  = ty * 4;
    const int c0s = tx * 4;
    const int c0o = tx * 8;

    float oacc[4][8];
#pragma unroll
    for (int i = 0; i < 4; i++)
#pragma unroll
        for (int j = 0; j < 8; j++) oacc[i][j] = 0.f;

    for (int j = 0; j <= qtile; j++) {
        const int j0 = j * 64;
        __syncthreads();

#pragma unroll
        for (int it = 0; it < 8; it++) {
            int i  = tid + it * 256;
            int r  = i >> 5;
            int c4 = (i & 31) << 2;
            float4 k4 = *(const float4*)(kbase + (size_t)(j0 + r) * KVDIM + c4);
            s.sKT[c4 + 0][r] = k4.x;
            s.sKT[c4 + 1][r] = k4.y;
            s.sKT[c4 + 2][r] = k4.z;
            s.sKT[c4 + 3][r] = k4.w;
            float4 v4 = *(const float4*)(vbase + (size_t)(j0 + r) * KVDIM + c4);
            *(float4*)&s.sV[r][c4] = v4;
        }
        __syncthreads();

        float acc[4][4];
#pragma unroll
        for (int i = 0; i < 4; i++)
#pragma unroll
            for (int c = 0; c < 4; c++) acc[i][c] = 0.f;

#pragma unroll 2
        for (int d4 = 0; d4 < HD; d4 += 4) {
            float qreg[4][4];
#pragma unroll
            for (int rr = 0; rr < 4; rr++)
                *(float4*)&qreg[rr][0] = *(const float4*)&s.sQ[r0 + rr][d4];
#pragma unroll
            for (int dd = 0; dd < 4; dd++) {
                float4 kv = *(const float4*)&s.sKT[d4 + dd][c0s];
                float kr[4] = {kv.x, kv.y, kv.z, kv.w};
#pragma unroll
                for (int rr = 0; rr < 4; rr++)
#pragma unroll
                    for (int cc = 0; cc < 4; cc++)
                        acc[rr][cc] += qreg[rr][dd] * kr[cc];
            }
        }

        if (j == qtile) {
#pragma unroll
            for (int rr = 0; rr < 4; rr++)
#pragma unroll
                for (int cc = 0; cc < 4; cc++)
                    if (j0 + c0s + cc > q0 + r0 + rr) acc[rr][cc] = -1e30f;
        }

#pragma unroll
        for (int rr = 0; rr < 4; rr++) {
            float tm0 = fmaxf(fmaxf(acc[rr][0], acc[rr][1]),
                              fmaxf(acc[rr][2], acc[rr][3]));
            s.sRed[r0 + rr][tx] = tm0;
        }
        __syncthreads();
        if (tid < 64) {
            float mx = s.sRed[tid][0];
#pragma unroll
            for (int t = 1; t < 16; t++) mx = fmaxf(mx, s.sRed[tid][t]);
            float mo = s.m_sh[tid];
            float mn = fmaxf(mo, mx);
            s.alpha_sh[tid] = __expf(mo - mn);
            s.m_sh[tid]     = mn;
        }
        __syncthreads();

#pragma unroll
        for (int rr = 0; rr < 4; rr++) {
            float mrow = s.m_sh[r0 + rr];
            float ps = 0.f;
#pragma unroll
            for (int cc = 0; cc < 4; cc++) {
                float p = __expf(acc[rr][cc] - mrow);
                ps += p;
                s.sP[r0 + rr][c0s + cc] = p;
            }
            s.sRed[r0 + rr][tx] = ps;
        }
#pragma unroll
        for (int rr = 0; rr < 4; rr++) {
            float a = s.alpha_sh[r0 + rr];
#pragma unroll
            for (int c = 0; c < 8; c++) oacc[rr][c] *= a;
        }
        __syncthreads();
        if (tid < 64) {
            float sm = 0.f;
#pragma unroll
            for (int t = 0; t < 16; t++) sm += s.sRed[tid][t];
            s.l_sh[tid] = s.l_sh[tid] * s.alpha_sh[tid] + sm;
        }

#pragma unroll 2
        for (int k4 = 0; k4 < 64; k4 += 4) {
            float preg[4][4];
#pragma unroll
            for (int rr = 0; rr < 4; rr++)
                *(float4*)&preg[rr][0] = *(const float4*)&s.sP[r0 + rr][k4];
#pragma unroll
            for (int dd = 0; dd < 4; dd++) {
                int kk = k4 + dd;
                float4 v0 = *(const float4*)&s.sV[kk][c0o];
                float4 v1 = *(const float4*)&s.sV[kk][c0o + 4];
                float vr[8] = {v0.x, v0.y, v0.z, v0.w, v1.x, v1.y, v1.z, v1.w};
#pragma unroll
                for (int rr = 0; rr < 4; rr++)
#pragma unroll
                    for (int c = 0; c < 8; c++)
                        oacc[rr][c] += preg[rr][dd] * vr[c];
            }
        }
    }

    __syncthreads();
#pragma unroll
    for (int rr = 0; rr < 4; rr++) {
        int row = r0 + rr;
        float inv = 1.f / s.l_sh[row];
        float4 o0, o1;
        o0.x = oacc[rr][0] * inv; o0.y = oacc[rr][1] * inv;
        o0.z = oacc[rr][2] * inv; o0.w = oacc[rr][3] * inv;
        o1.x = oacc[rr][4] * inv; o1.y = oacc[rr][5] * inv;
        o1.z = oacc[rr][6] * inv; o1.w = oacc[rr][7] * inv;
        float* op = obase + (size_t)(q0 + row) * DIM + c0o;
        *(float4*)(op)     = o0;
        *(float4*)(op + 4) = o1;
    }
}

// ---------------- launch ----------------
extern "C" void kernel_launch(void* const* d_in, const int* in_sizes, int n_in,
                              void* d_out, int out_size)
{
    const float* enc  = (const float*)d_in[0];
    const float* dec  = (const float*)d_in[1];
    const float* W_kv = (const float*)d_in[2];
    const float* b_kv = (const float*)d_in[3];
    const float* W_q  = (const float*)d_in[4];
    const float* b_q  = (const float*)d_in[5];
    const float* W_o  = (const float*)d_in[6];
    const float* b_o  = (const float*)d_in[7];
    float* out = (float*)d_out;

    float *p_kv, *p_q, *p_ao;
    __nv_bfloat16 *p_Ah, *p_Al, *p_Wh, *p_Wl;
    cudaGetSymbolAddress((void**)&p_kv, g_kv);
    cudaGetSymbolAddress((void**)&p_q,  g_q);
    cudaGetSymbolAddress((void**)&p_ao, g_ao);
    cudaGetSymbolAddress((void**)&p_Ah, g_Ah);
    cudaGetSymbolAddress((void**)&p_Al, g_Al);
    cudaGetSymbolAddress((void**)&p_Wh, g_Wh);
    cudaGetSymbolAddress((void**)&p_Wl, g_Wl);

    cudaFuncSetAttribute(attn_kernel, cudaFuncAttributeMaxDynamicSharedMemorySize,
                         (int)sizeof(AttnSmem));
    cudaFuncSetAttribute(gemm_tc_kernel, cudaFuncAttributeMaxDynamicSharedMemorySize,
                         GEMM_SMEM);

    const int nA4 = MROWS * DIM / 4;

    // ---- GEMM 1: kv = enc @ W_kv + b_kv  (M=8192, N=4096, K=2048) ----
    conv_w_kernel<<<dim3(KVDIM / 32, DIM / 32), dim3(32, 8)>>>(W_kv, p_Wh, p_Wl, DIM, KVDIM);
    conv_split_kernel<<<(nA4 + 255) / 256, 256>>>(enc, p_Ah, p_Al, nA4);
    gemm_tc_kernel<<<dim3(KVDIM / 128, MROWS / 128), 256, GEMM_SMEM>>>(
        p_Ah, p_Al, p_Wh, p_Wl, b_kv, p_kv, KVDIM);

    // ---- GEMM 2: q = dec @ W_q + b_q  (M=8192, N=2048, K=2048) ----
    conv_w_kernel<<<dim3(DIM / 32, DIM / 32), dim3(32, 8)>>>(W_q, p_Wh, p_Wl, DIM, DIM);
    conv_split_kernel<<<(nA4 + 255) / 256, 256>>>(dec, p_Ah, p_Al, nA4);
    gemm_tc_kernel<<<dim3(DIM / 128, MROWS / 128), 256, GEMM_SMEM>>>(
        p_Ah, p_Al, p_Wh, p_Wl, b_q, p_q, DIM);

    // ---- attention (fp32) ----
    attn_kernel<<<dim3(TSEQ / 64, BATCH * NHEAD), 256, sizeof(AttnSmem)>>>(
        p_q, p_kv, p_ao);

    // ---- GEMM 3: out = ao @ W_o + b_o  (M=8192, N=2048, K=2048) ----
    conv_w_kernel<<<dim3(DIM / 32, DIM / 32), dim3(32, 8)>>>(W_o, p_Wh, p_Wl, DIM, DIM);
    conv_split_kernel<<<(nA4 + 255) / 256, 256>>>(p_ao, p_Ah, p_Al, nA4);
    gemm_tc_kernel<<<dim3(DIM / 128, MROWS / 128), 256, GEMM_SMEM>>>(
        p_Ah, p_Al, p_Wh, p_Wl, b_o, out, DIM);
}

// round 4
// speedup vs baseline: 1.9019x; 1.1325x over previous
#include <cuda_runtime.h>
#include <cuda_fp16.h>
#include <cstdint>

#define TSEQ   2048
#define BATCH  4
#define NHEAD  16
#define HD     128
#define DIM    2048
#define MROWS  (BATCH * TSEQ)   // 8192
#define KVDIM  (2 * DIM)        // 4096

// ---------------- scratch (allocation-free: __device__ globals) ----------------
__device__ float g_kv[(size_t)MROWS * KVDIM];
__device__ float g_q [(size_t)MROWS * DIM];
__device__ float g_ao[(size_t)MROWS * DIM];
__device__ __half g_Ah[(size_t)MROWS * DIM];   // activation hi (fp16)
__device__ __half g_Al[(size_t)MROWS * DIM];   // activation lo (fp16, exact residual)
__device__ __half g_Wh[(size_t)KVDIM * DIM];   // weight hi (fp16), [N,K] layout

// ---------------- helpers ----------------
__device__ __forceinline__ uint32_t smem_u32(const void* p) {
    uint32_t a;
    asm("{ .reg .u64 t; cvta.to.shared.u64 t, %1; cvt.u32.u64 %0, t; }"
        : "=r"(a) : "l"(p));
    return a;
}

__device__ __forceinline__ void ldmatrix_x4(uint32_t* r, uint32_t addr) {
    asm volatile("ldmatrix.sync.aligned.m8n8.x4.shared.b16 {%0,%1,%2,%3}, [%4];"
                 : "=r"(r[0]), "=r"(r[1]), "=r"(r[2]), "=r"(r[3]) : "r"(addr));
}

__device__ __forceinline__ void mma_fp16(float* d, const uint32_t* a, const uint32_t* b) {
    asm volatile(
        "mma.sync.aligned.m16n8k16.row.col.f32.f16.f16.f32 "
        "{%0,%1,%2,%3}, {%4,%5,%6,%7}, {%8,%9}, {%0,%1,%2,%3};"
        : "+f"(d[0]), "+f"(d[1]), "+f"(d[2]), "+f"(d[3])
        : "r"(a[0]), "r"(a[1]), "r"(a[2]), "r"(a[3]), "r"(b[0]), "r"(b[1]));
}

// ---------------- conversion kernels ----------------
// fp32 -> (hi, lo) fp16, elementwise
__global__ __launch_bounds__(256) void conv_split_kernel(
    const float* __restrict__ x, __half* __restrict__ h,
    __half* __restrict__ l, int n4)
{
    int i = blockIdx.x * 256 + threadIdx.x;
    if (i >= n4) return;
    float4 v = ((const float4*)x)[i];
    float a[4] = {v.x, v.y, v.z, v.w};
    __half hh[4], ll[4];
#pragma unroll
    for (int k = 0; k < 4; k++) {
        hh[k] = __float2half(a[k]);
        ll[k] = __float2half(a[k] - __half2float(hh[k]));
    }
    __half2* hp = (__half2*)(h + (size_t)i * 4);
    __half2* lp = (__half2*)(l + (size_t)i * 4);
    hp[0] = __half2{hh[0], hh[1]};
    hp[1] = __half2{hh[2], hh[3]};
    lp[0] = __half2{ll[0], ll[1]};
    lp[1] = __half2{ll[2], ll[3]};
}

// fp32 W[K,N] -> fp16 [N,K] (transpose), hi only
__global__ __launch_bounds__(256) void conv_w_kernel(
    const float* __restrict__ W, __half* __restrict__ Wh, int K, int N)
{
    __shared__ float t[32][33];
    int n0 = blockIdx.x * 32, k0 = blockIdx.y * 32;
    int tx = threadIdx.x, ty = threadIdx.y;   // 32 x 8
#pragma unroll
    for (int r = 0; r < 4; r++)
        t[ty + 8 * r][tx] = W[(size_t)(k0 + ty + 8 * r) * N + n0 + tx];
    __syncthreads();
#pragma unroll
    for (int r = 0; r < 4; r++) {
        float v = t[tx][ty + 8 * r];
        int n = n0 + ty + 8 * r;
        Wh[(size_t)n * K + k0 + tx] = __float2half(v);
    }
}

// ---------------- mma.sync GEMM (fp16, 2-pass split) ----------------
// C[M,N] = Ah[M,2048]@Wh[N,2048]^T + Al@Wh^T + bias
// CTA 128x128, BK=64, double buffered. 256 threads = 8 warps, warp tile 64x32.
#define BK       64
#define ASTRIDE  72                       // fp16 elements per smem row
#define ROWB     (ASTRIDE * 2)            // 144 bytes
#define ATILE_B  (128 * ROWB)             // 18432
#define BUF_B    (2 * ATILE_B)            // 36864 per buffer
#define GEMM_SMEM (2 * BUF_B)             // 73728
#define NCH 64                            // 2 passes * 32 K-chunks

__global__ __launch_bounds__(256) void gemm_tc_kernel(
    const __half* __restrict__ Ah, const __half* __restrict__ Al,
    const __half* __restrict__ Wh,
    const float* __restrict__ bias, float* __restrict__ C, int N)
{
    extern __shared__ char smem[];
    const uint32_t sbase = smem_u32(smem);
    const int tid  = threadIdx.x;
    const int wid  = tid >> 5;
    const int lane = tid & 31;
    const int wm   = wid & 1;        // 2 warps in M
    const int wn   = wid >> 1;       // 4 warps in N
    const int bm   = blockIdx.y * 128;
    const int bn   = blockIdx.x * 128;

    const __half* APs[2] = {Ah, Al};

    float acc[4][4][4];
#pragma unroll
    for (int i = 0; i < 4; i++)
#pragma unroll
        for (int j = 0; j < 4; j++)
#pragma unroll
            for (int k = 0; k < 4; k++) acc[i][j][k] = 0.f;

    const uint32_t a_lane_off = (uint32_t)((lane & 15) * ROWB + ((lane >> 4) << 3) * 2);
    const uint32_t b_lane_off = (uint32_t)((lane >> 2) * ROWB + (lane & 3) * 4);
    const uint32_t a_warp_base = (uint32_t)(wm * 64) * ROWB;
    const uint32_t b_warp_base = (uint32_t)(ATILE_B + (wn * 32) * ROWB);

    auto load_chunk = [&](int ci, int buf) {
        const int pass = ci >> 5;
        const int k0 = (ci & 31) * BK;
        const __half* Ap = APs[pass];
        const uint32_t base = sbase + (uint32_t)buf * BUF_B;
#pragma unroll
        for (int j = 0; j < 8; j++) {
            int c = j * 256 + tid;          // 0..2047
            int row = (c >> 3) & 127;
            int c16 = c & 7;
            uint32_t dst;
            const __half* g;
            if (c < 1024) {
                dst = base + (uint32_t)(row * ROWB + c16 * 16);
                g = Ap + (size_t)(bm + row) * DIM + k0 + c16 * 8;
            } else {
                dst = base + (uint32_t)(ATILE_B + row * ROWB + c16 * 16);
                g = Wh + (size_t)(bn + row) * DIM + k0 + c16 * 8;
            }
            asm volatile("cp.async.cg.shared.global [%0], [%1], 16;" :: "r"(dst), "l"(g));
        }
        asm volatile("cp.async.commit_group;");
    };

    load_chunk(0, 0);

    for (int i = 0; i < NCH; i++) {
        const int b = i & 1;
        const bool has_next = (i + 1 < NCH);
        if (has_next) load_chunk(i + 1, b ^ 1);
        if (has_next) asm volatile("cp.async.wait_group 1;");
        else          asm volatile("cp.async.wait_group 0;");
        __syncthreads();

        const uint32_t abuf = sbase + (uint32_t)b * BUF_B;
#pragma unroll
        for (int ks = 0; ks < 4; ks++) {
            uint32_t afrag[4][4];
#pragma unroll
            for (int mf = 0; mf < 4; mf++)
                ldmatrix_x4(afrag[mf],
                            abuf + a_warp_base + (uint32_t)(mf * 16 * ROWB)
                                 + (uint32_t)(ks * 32) + a_lane_off);
            uint32_t bfrag[4][2];
#pragma unroll
            for (int nf = 0; nf < 4; nf++) {
                uint32_t boff = (uint32_t)b * BUF_B + b_warp_base
                              + (uint32_t)(nf * 8 * ROWB) + (uint32_t)(ks * 32) + b_lane_off;
                bfrag[nf][0] = *(const uint32_t*)(smem + boff);
                bfrag[nf][1] = *(const uint32_t*)(smem + boff + 16);
            }
#pragma unroll
            for (int mf = 0; mf < 4; mf++)
#pragma unroll
                for (int nf = 0; nf < 4; nf++)
                    mma_fp16(acc[mf][nf], afrag[mf], bfrag[nf]);
        }
        __syncthreads();
    }

    // epilogue: bias + store
    float2 bfr[4];
#pragma unroll
    for (int nf = 0; nf < 4; nf++) {
        int col = bn + wn * 32 + nf * 8 + (lane & 3) * 2;
        bfr[nf].x = __ldg(bias + col);
        bfr[nf].y = __ldg(bias + col + 1);
    }
#pragma unroll
    for (int mf = 0; mf < 4; mf++) {
#pragma unroll
        for (int h = 0; h < 2; h++) {
            int row = bm + wm * 64 + mf * 16 + (lane >> 2) + h * 8;
            float* crow = C + (size_t)row * N + bn + wn * 32;
#pragma unroll
            for (int nf = 0; nf < 4; nf++) {
                float2 v;
                v.x = acc[mf][nf][2 * h + 0] + bfr[nf].x;
                v.y = acc[mf][nf][2 * h + 1] + bfr[nf].y;
                *(float2*)(crow + nf * 8 + (lane & 3) * 2) = v;
            }
        }
    }
}

// ---------------- Flash attention (causal, fp32, online softmax) ----------------
struct __align__(16) AttnSmem {
    float sQ [64][132];
    float sKT[128][68];
    float sV [64][128];
    float sP [64][68];
    float sRed[64][16];
    float m_sh[64];
    float l_sh[64];
    float alpha_sh[64];
};

__global__ __launch_bounds__(256) void attn_kernel(
    const float* __restrict__ qbuf, const float* __restrict__ kvbuf,
    float* __restrict__ aobuf)
{
    extern __shared__ char smem_raw[];
    AttnSmem& s = *reinterpret_cast<AttnSmem*>(smem_raw);

    const int tid   = threadIdx.x;
    const int qtile = blockIdx.x;
    const int bh    = blockIdx.y;
    const int b     = bh >> 4;
    const int h     = bh & 15;
    const int q0    = qtile * 64;
    const float scale = 0.08838834764831845f;

    const float* qbase = qbuf  + (size_t)b * TSEQ * DIM   + (size_t)h * HD;
    const float* kbase = kvbuf + (size_t)b * TSEQ * KVDIM + (size_t)h * HD;
    const float* vbase = kbase + DIM;
    float*       obase = aobuf + (size_t)b * TSEQ * DIM   + (size_t)h * HD;

#pragma unroll
    for (int it = 0; it < 8; it++) {
        int i  = tid + it * 256;
        int r  = i >> 5;
        int c4 = (i & 31) << 2;
        float4 v = *(const float4*)(qbase + (size_t)(q0 + r) * DIM + c4);
        s.sQ[r][c4 + 0] = v.x * scale;
        s.sQ[r][c4 + 1] = v.y * scale;
        s.sQ[r][c4 + 2] = v.z * scale;
        s.sQ[r][c4 + 3] = v.w * scale;
    }
    if (tid < 64) { s.m_sh[tid] = -1e30f; s.l_sh[tid] = 0.f; }

    const int ty  = tid >> 4;
    const int tx  = tid & 15;
    const int r0  = ty * 4;
    const int c0s = tx * 4;
    const int c0o = tx * 8;

    float oacc[4][8];
#pragma unroll
    for (int i = 0; i < 4; i++)
#pragma unroll
        for (int j = 0; j < 8; j++) oacc[i][j] = 0.f;

    for (int j = 0; j <= qtile; j++) {
        const int j0 = j * 64;
        __syncthreads();

#pragma unroll
        for (int it = 0; it < 8; it++) {
            int i  = tid + it * 256;
            int r  = i >> 5;
            int c4 = (i & 31) << 2;
            float4 k4 = *(const float4*)(kbase + (size_t)(j0 + r) * KVDIM + c4);
            s.sKT[c4 + 0][r] = k4.x;
            s.sKT[c4 + 1][r] = k4.y;
            s.sKT[c4 + 2][r] = k4.z;
            s.sKT[c4 + 3][r] = k4.w;
            float4 v4 = *(const float4*)(vbase + (size_t)(j0 + r) * KVDIM + c4);
            *(float4*)&s.sV[r][c4] = v4;
        }
        __syncthreads();

        float acc[4][4];
#pragma unroll
        for (int i = 0; i < 4; i++)
#pragma unroll
            for (int c = 0; c < 4; c++) acc[i][c] = 0.f;

#pragma unroll 2
        for (int d4 = 0; d4 < HD; d4 += 4) {
            float qreg[4][4];
#pragma unroll
            for (int rr = 0; rr < 4; rr++)
                *(float4*)&qreg[rr][0] = *(const float4*)&s.sQ[r0 + rr][d4];
#pragma unroll
            for (int dd = 0; dd < 4; dd++) {
                float4 kv = *(const float4*)&s.sKT[d4 + dd][c0s];
                float kr[4] = {kv.x, kv.y, kv.z, kv.w};
#pragma unroll
                for (int rr = 0; rr < 4; rr++)
#pragma unroll
                    for (int cc = 0; cc < 4; cc++)
                        acc[rr][cc] += qreg[rr][dd] * kr[cc];
            }
        }

        if (j == qtile) {
#pragma unroll
            for (int rr = 0; rr < 4; rr++)
#pragma unroll
                for (int cc = 0; cc < 4; cc++)
                    if (j0 + c0s + cc > q0 + r0 + rr) acc[rr][cc] = -1e30f;
        }

#pragma unroll
        for (int rr = 0; rr < 4; rr++) {
            float tm0 = fmaxf(fmaxf(acc[rr][0], acc[rr][1]),
                              fmaxf(acc[rr][2], acc[rr][3]));
            s.sRed[r0 + rr][tx] = tm0;
        }
        __syncthreads();
        if (tid < 64) {
            float mx = s.sRed[tid][0];
#pragma unroll
            for (int t = 1; t < 16; t++) mx = fmaxf(mx, s.sRed[tid][t]);
            float mo = s.m_sh[tid];
            float mn = fmaxf(mo, mx);
            s.alpha_sh[tid] = __expf(mo - mn);
            s.m_sh[tid]     = mn;
        }
        __syncthreads();

#pragma unroll
        for (int rr = 0; rr < 4; rr++) {
            float mrow = s.m_sh[r0 + rr];
            float ps = 0.f;
#pragma unroll
            for (int cc = 0; cc < 4; cc++) {
                float p = __expf(acc[rr][cc] - mrow);
                ps += p;
                s.sP[r0 + rr][c0s + cc] = p;
            }
            s.sRed[r0 + rr][tx] = ps;
        }
#pragma unroll
        for (int rr = 0; rr < 4; rr++) {
            float a = s.alpha_sh[r0 + rr];
#pragma unroll
            for (int c = 0; c < 8; c++) oacc[rr][c] *= a;
        }
        __syncthreads();
        if (tid < 64) {
            float sm = 0.f;
#pragma unroll
            for (int t = 0; t < 16; t++) sm += s.sRed[tid][t];
            s.l_sh[tid] = s.l_sh[tid] * s.alpha_sh[tid] + sm;
        }

#pragma unroll 2
        for (int k4 = 0; k4 < 64; k4 += 4) {
            float preg[4][4];
#pragma unroll
            for (int rr = 0; rr < 4; rr++)
                *(float4*)&preg[rr][0] = *(const float4*)&s.sP[r0 + rr][k4];
#pragma unroll
            for (int dd = 0; dd < 4; dd++) {
                int kk = k4 + dd;
                float4 v0 = *(const float4*)&s.sV[kk][c0o];
                float4 v1 = *(const float4*)&s.sV[kk][c0o + 4];
                float vr[8] = {v0.x, v0.y, v0.z, v0.w, v1.x, v1.y, v1.z, v1.w};
#pragma unroll
                for (int rr = 0; rr < 4; rr++)
#pragma unroll
                    for (int c = 0; c < 8; c++)
                        oacc[rr][c] += preg[rr][dd] * vr[c];
            }
        }
    }

    __syncthreads();
#pragma unroll
    for (int rr = 0; rr < 4; rr++) {
        int row = r0 + rr;
        float inv = 1.f / s.l_sh[row];
        float4 o0, o1;
        o0.x = oacc[rr][0] * inv; o0.y = oacc[rr][1] * inv;
        o0.z = oacc[rr][2] * inv; o0.w = oacc[rr][3] * inv;
        o1.x = oacc[rr][4] * inv; o1.y = oacc[rr][5] * inv;
        o1.z = oacc[rr][6] * inv; o1.w = oacc[rr][7] * inv;
        float* op = obase + (size_t)(q0 + row) * DIM + c0o;
        *(float4*)(op)     = o0;
        *(float4*)(op + 4) = o1;
    }
}

// ---------------- launch ----------------
extern "C" void kernel_launch(void* const* d_in, const int* in_sizes, int n_in,
                              void* d_out, int out_size)
{
    const float* enc  = (const float*)d_in[0];
    const float* dec  = (const float*)d_in[1];
    const float* W_kv = (const float*)d_in[2];
    const float* b_kv = (const float*)d_in[3];
    const float* W_q  = (const float*)d_in[4];
    const float* b_q  = (const float*)d_in[5];
    const float* W_o  = (const float*)d_in[6];
    const float* b_o  = (const float*)d_in[7];
    float* out = (float*)d_out;

    float *p_kv, *p_q, *p_ao;
    __half *p_Ah, *p_Al, *p_Wh;
    cudaGetSymbolAddress((void**)&p_kv, g_kv);
    cudaGetSymbolAddress((void**)&p_q,  g_q);
    cudaGetSymbolAddress((void**)&p_ao, g_ao);
    cudaGetSymbolAddress((void**)&p_Ah, g_Ah);
    cudaGetSymbolAddress((void**)&p_Al, g_Al);
    cudaGetSymbolAddress((void**)&p_Wh, g_Wh);

    cudaFuncSetAttribute(attn_kernel, cudaFuncAttributeMaxDynamicSharedMemorySize,
                         (int)sizeof(AttnSmem));
    cudaFuncSetAttribute(gemm_tc_kernel, cudaFuncAttributeMaxDynamicSharedMemorySize,
                         GEMM_SMEM);

    const int nA4 = MROWS * DIM / 4;

    // ---- GEMM 1: kv = enc @ W_kv + b_kv  (M=8192, N=4096, K=2048) ----
    conv_w_kernel<<<dim3(KVDIM / 32, DIM / 32), dim3(32, 8)>>>(W_kv, p_Wh, DIM, KVDIM);
    conv_split_kernel<<<(nA4 + 255) / 256, 256>>>(enc, p_Ah, p_Al, nA4);
    gemm_tc_kernel<<<dim3(KVDIM / 128, MROWS / 128), 256, GEMM_SMEM>>>(
        p_Ah, p_Al, p_Wh, b_kv, p_kv, KVDIM);

    // ---- GEMM 2: q = dec @ W_q + b_q  (M=8192, N=2048, K=2048) ----
    conv_w_kernel<<<dim3(DIM / 32, DIM / 32), dim3(32, 8)>>>(W_q, p_Wh, DIM, DIM);
    conv_split_kernel<<<(nA4 + 255) / 256, 256>>>(dec, p_Ah, p_Al, nA4);
    gemm_tc_kernel<<<dim3(DIM / 128, MROWS / 128), 256, GEMM_SMEM>>>(
        p_Ah, p_Al, p_Wh, b_q, p_q, DIM);

    // ---- attention (fp32) ----
    attn_kernel<<<dim3(TSEQ / 64, BATCH * NHEAD), 256, sizeof(AttnSmem)>>>(
        p_q, p_kv, p_ao);

    // ---- GEMM 3: out = ao @ W_o + b_o  (M=8192, N=2048, K=2048) ----
    conv_w_kernel<<<dim3(DIM / 32, DIM / 32), dim3(32, 8)>>>(W_o, p_Wh, DIM, DIM);
    conv_split_kernel<<<(nA4 + 255) / 256, 256>>>(p_ao, p_Ah, p_Al, nA4);
    gemm_tc_kernel<<<dim3(DIM / 128, MROWS / 128), 256, GEMM_SMEM>>>(
        p_Ah, p_Al, p_Wh, b_o, out, DIM);
}

// round 5
// speedup vs baseline: 4.0413x; 2.1249x over previous
#include <cuda_runtime.h>
#include <cuda_fp16.h>
#include <cstdint>

#define TSEQ   2048
#define BATCH  4
#define NHEAD  16
#define HD     128
#define DIM    2048
#define MROWS  (BATCH * TSEQ)   // 8192
#define KVDIM  (2 * DIM)        // 4096

// ---------------- scratch (allocation-free: __device__ globals) ----------------
__device__ __half g_Ah [(size_t)MROWS * DIM];   // activation hi (fp16)
__device__ __half g_Al [(size_t)MROWS * DIM];   // activation lo
__device__ __half g_Wh [(size_t)KVDIM * DIM];   // weight fp16, [N,K]
__device__ __half g_K16[(size_t)MROWS * DIM];   // K fp16
__device__ __half g_V16[(size_t)MROWS * DIM];   // V fp16
__device__ __half g_Qh [(size_t)MROWS * DIM];   // scaled q hi
__device__ __half g_Ql [(size_t)MROWS * DIM];   // scaled q lo

// ---------------- helpers ----------------
__device__ __forceinline__ uint32_t smem_u32(const void* p) {
    uint32_t a;
    asm("{ .reg .u64 t; cvta.to.shared.u64 t, %1; cvt.u32.u64 %0, t; }"
        : "=r"(a) : "l"(p));
    return a;
}
#define CP_ASYNC16(dst, src) \
    asm volatile("cp.async.cg.shared.global [%0], [%1], 16;" :: "r"(dst), "l"(src))

__device__ __forceinline__ void ldmatrix_x4(uint32_t* r, uint32_t addr) {
    asm volatile("ldmatrix.sync.aligned.m8n8.x4.shared.b16 {%0,%1,%2,%3}, [%4];"
                 : "=r"(r[0]), "=r"(r[1]), "=r"(r[2]), "=r"(r[3]) : "r"(addr));
}
__device__ __forceinline__ void ldmatrix_x4_trans(uint32_t* r, uint32_t addr) {
    asm volatile("ldmatrix.sync.aligned.m8n8.x4.trans.shared.b16 {%0,%1,%2,%3}, [%4];"
                 : "=r"(r[0]), "=r"(r[1]), "=r"(r[2]), "=r"(r[3]) : "r"(addr));
}
__device__ __forceinline__ uint32_t lds32(uint32_t a) {
    uint32_t v; asm volatile("ld.shared.b32 %0, [%1];" : "=r"(v) : "r"(a)); return v;
}
__device__ __forceinline__ void sts32(uint32_t a, uint32_t v) {
    asm volatile("st.shared.b32 [%0], %1;" :: "r"(a), "r"(v));
}
__device__ __forceinline__ void mma_fp16(float* d, const uint32_t* a, const uint32_t* b) {
    asm volatile(
        "mma.sync.aligned.m16n8k16.row.col.f32.f16.f16.f32 "
        "{%0,%1,%2,%3}, {%4,%5,%6,%7}, {%8,%9}, {%0,%1,%2,%3};"
        : "+f"(d[0]), "+f"(d[1]), "+f"(d[2]), "+f"(d[3])
        : "r"(a[0]), "r"(a[1]), "r"(a[2]), "r"(a[3]), "r"(b[0]), "r"(b[1]));
}

// fast exp2 on FMA pipe (t <= ~0); poly on [-0.5,0.5] scaled by sqrt(2)
__device__ __forceinline__ float exp2p(float t) {
    t = fmaxf(t, -126.f);
    float fi = floorf(t);
    float x = t - fi - 0.5f;
    float p = 0.001885630f;
    p = fmaf(p, x, 0.013602145f);
    p = fmaf(p, x, 0.078494717f);
    p = fmaf(p, x, 0.339731669f);
    p = fmaf(p, x, 0.980258143f);
    p = fmaf(p, x, 1.414213562f);
    int e = (int)fi;
    return __int_as_float(__float_as_int(p) + (e << 23));
}

// ---------------- conversion kernels ----------------
__global__ __launch_bounds__(256) void conv_split_kernel(
    const float* __restrict__ x, __half* __restrict__ h,
    __half* __restrict__ l, int n4)
{
    int i = blockIdx.x * 256 + threadIdx.x;
    if (i >= n4) return;
    float4 v = ((const float4*)x)[i];
    float a[4] = {v.x, v.y, v.z, v.w};
    __half hh[4], ll[4];
#pragma unroll
    for (int k = 0; k < 4; k++) {
        hh[k] = __float2half(a[k]);
        ll[k] = __float2half(a[k] - __half2float(hh[k]));
    }
    __half2* hp = (__half2*)(h + (size_t)i * 4);
    __half2* lp = (__half2*)(l + (size_t)i * 4);
    hp[0] = __half2{hh[0], hh[1]};
    hp[1] = __half2{hh[2], hh[3]};
    lp[0] = __half2{ll[0], ll[1]};
    lp[1] = __half2{ll[2], ll[3]};
}

__global__ __launch_bounds__(256) void conv_w_kernel(
    const float* __restrict__ W, __half* __restrict__ Wh, int K, int N)
{
    __shared__ float t[32][33];
    int n0 = blockIdx.x * 32, k0 = blockIdx.y * 32;
    int tx = threadIdx.x, ty = threadIdx.y;
#pragma unroll
    for (int r = 0; r < 4; r++)
        t[ty + 8 * r][tx] = W[(size_t)(k0 + ty + 8 * r) * N + n0 + tx];
    __syncthreads();
#pragma unroll
    for (int r = 0; r < 4; r++) {
        float v = t[tx][ty + 8 * r];
        Wh[(size_t)(n0 + ty + 8 * r) * K + k0 + tx] = __float2half(v);
    }
}

// ---------------- mma.sync GEMM (fp16, 2-pass split), templated epilogue ----------------
// MODE 0: fp32 C = acc + bias           (outA = float* C)
// MODE 1: fp16 K/V split by column      (outA = K16, outB = V16)
// MODE 2: fp16 scaled split q           (outA = Qh,  outB = Ql)
#define BKG      64
#define ASTRIDE  72
#define ROWB     (ASTRIDE * 2)            // 144 B
#define ATILE_B  (128 * ROWB)
#define BUF_B    (2 * ATILE_B)
#define GEMM_SMEM (2 * BUF_B)             // 73728
#define NCH 64

template<int MODE>
__global__ __launch_bounds__(256) void gemm_tc_kernel(
    const __half* __restrict__ Ah, const __half* __restrict__ Al,
    const __half* __restrict__ Wh,
    const float* __restrict__ bias, void* outA, void* outB, int N)
{
    extern __shared__ char smem[];
    const uint32_t sbase = smem_u32(smem);
    const int tid  = threadIdx.x;
    const int wid  = tid >> 5;
    const int lane = tid & 31;
    const int wm   = wid & 1;
    const int wn   = wid >> 1;
    const int bm   = blockIdx.y * 128;
    const int bn   = blockIdx.x * 128;

    const __half* APs[2] = {Ah, Al};

    float acc[4][4][4];
#pragma unroll
    for (int i = 0; i < 4; i++)
#pragma unroll
        for (int j = 0; j < 4; j++)
#pragma unroll
            for (int k = 0; k < 4; k++) acc[i][j][k] = 0.f;

    const uint32_t a_lane_off = (uint32_t)((lane & 15) * ROWB + ((lane >> 4) << 3) * 2);
    const uint32_t b_lane_off = (uint32_t)((lane >> 2) * ROWB + (lane & 3) * 4);
    const uint32_t a_warp_base = (uint32_t)(wm * 64) * ROWB;
    const uint32_t b_warp_base = (uint32_t)(ATILE_B + (wn * 32) * ROWB);

    auto load_chunk = [&](int ci, int buf) {
        const int pass = ci >> 5;
        const int k0 = (ci & 31) * BKG;
        const __half* Ap = APs[pass];
        const uint32_t base = sbase + (uint32_t)buf * BUF_B;
#pragma unroll
        for (int j = 0; j < 8; j++) {
            int c = j * 256 + tid;
            int row = (c >> 3) & 127;
            int c16 = c & 7;
            uint32_t dst;
            const __half* g;
            if (c < 1024) {
                dst = base + (uint32_t)(row * ROWB + c16 * 16);
                g = Ap + (size_t)(bm + row) * DIM + k0 + c16 * 8;
            } else {
                dst = base + (uint32_t)(ATILE_B + row * ROWB + c16 * 16);
                g = Wh + (size_t)(bn + row) * DIM + k0 + c16 * 8;
            }
            CP_ASYNC16(dst, g);
        }
        asm volatile("cp.async.commit_group;");
    };

    load_chunk(0, 0);

    for (int i = 0; i < NCH; i++) {
        const int b = i & 1;
        const bool has_next = (i + 1 < NCH);
        if (has_next) load_chunk(i + 1, b ^ 1);
        if (has_next) asm volatile("cp.async.wait_group 1;");
        else          asm volatile("cp.async.wait_group 0;");
        __syncthreads();

        const uint32_t abuf = sbase + (uint32_t)b * BUF_B;
#pragma unroll
        for (int ks = 0; ks < 4; ks++) {
            uint32_t afrag[4][4];
#pragma unroll
            for (int mf = 0; mf < 4; mf++)
                ldmatrix_x4(afrag[mf],
                            abuf + a_warp_base + (uint32_t)(mf * 16 * ROWB)
                                 + (uint32_t)(ks * 32) + a_lane_off);
            uint32_t bfrag[4][2];
#pragma unroll
            for (int nf = 0; nf < 4; nf++) {
                uint32_t boff = abuf + b_warp_base
                              + (uint32_t)(nf * 8 * ROWB) + (uint32_t)(ks * 32) + b_lane_off;
                bfrag[nf][0] = lds32(boff);
                bfrag[nf][1] = lds32(boff + 16);
            }
#pragma unroll
            for (int mf = 0; mf < 4; mf++)
#pragma unroll
                for (int nf = 0; nf < 4; nf++)
                    mma_fp16(acc[mf][nf], afrag[mf], bfrag[nf]);
        }
        __syncthreads();
    }

    // ---- epilogue ----
    const float CSCL = (float)(0.08838834764831845 * 1.4426950408889634);
    float2 bfr[4];
#pragma unroll
    for (int nf = 0; nf < 4; nf++) {
        int col = bn + wn * 32 + nf * 8 + (lane & 3) * 2;
        bfr[nf].x = __ldg(bias + col);
        bfr[nf].y = __ldg(bias + col + 1);
    }
#pragma unroll
    for (int mf = 0; mf < 4; mf++) {
#pragma unroll
        for (int h8 = 0; h8 < 2; h8++) {
            int row = bm + wm * 64 + mf * 16 + (lane >> 2) + h8 * 8;
#pragma unroll
            for (int nf = 0; nf < 4; nf++) {
                float vx = acc[mf][nf][2 * h8 + 0] + bfr[nf].x;
                float vy = acc[mf][nf][2 * h8 + 1] + bfr[nf].y;
                int coff = wn * 32 + nf * 8 + (lane & 3) * 2;
                if (MODE == 0) {
                    float* C = (float*)outA;
                    float2 o; o.x = vx; o.y = vy;
                    *(float2*)(C + (size_t)row * N + bn + coff) = o;
                } else if (MODE == 1) {
                    __half* dst = (bn < DIM) ? (__half*)outA : (__half*)outB;
                    int cb = (bn & (DIM - 1)) + coff;
                    *(__half2*)(dst + (size_t)row * DIM + cb) =
                        __floats2half2_rn(vx, vy);
                } else {
                    float qx = vx * CSCL, qy = vy * CSCL;
                    __half hx = __float2half_rn(qx), hy = __float2half_rn(qy);
                    size_t adr = (size_t)row * DIM + bn + coff;
                    *(__half2*)((__half*)outA + adr) = __halves2half2(hx, hy);
                    *(__half2*)((__half*)outB + adr) =
                        __floats2half2_rn(qx - __half2float(hx), qy - __half2float(hy));
                }
            }
        }
    }
}

// ---------------- fp16 tensor-core flash attention ----------------
// BM=64 q rows, BN=64 keys, 8 warps (4 M x 2 N). 2 CTAs/SM.
// smem byte offsets (row stride 272 B = 136 fp16 for 128-col tiles)
#define SM_QH   0
#define SM_QL   17408
#define SM_K0   34816
#define SM_K1   52224
#define SM_V    69632
#define SM_P    87040          // 64 x 144B
#define SM_RMAX 96256          // 64 x 2 floats
#define SM_RSUM 96768
#define ATT_SMEM 97280

__global__ __launch_bounds__(256, 2) void attn_tc_kernel(
    const __half* __restrict__ Qh, const __half* __restrict__ Ql,
    const __half* __restrict__ K16, const __half* __restrict__ V16,
    __half* __restrict__ OAh, __half* __restrict__ OAl)
{
    extern __shared__ char smem[];
    const uint32_t sb = smem_u32(smem);
    const int tid = threadIdx.x, lane = tid & 31, wid = tid >> 5;
    const int wm = wid & 3, wn = wid >> 2;
    const int qt = (int)gridDim.x - 1 - (int)blockIdx.x;   // heavy tiles first
    const int bh = blockIdx.y, bb = bh >> 4, hh = bh & 15;
    const int q0 = qt * 64;
    const size_t rowbase = (size_t)bb * TSEQ;
    const int hoff = hh * HD;

    float* sRMax = (float*)(smem + SM_RMAX);
    float* sRSum = (float*)(smem + SM_RSUM);

    // ---- Q loads (one group) ----
#pragma unroll
    for (int it = 0; it < 4; it++) {
        int idx = tid + it * 256; int r = idx >> 4, sg = idx & 15;
        CP_ASYNC16(sb + SM_QH + r * 272 + sg * 16,
                   Qh + (rowbase + q0 + r) * DIM + hoff + sg * 8);
    }
#pragma unroll
    for (int it = 0; it < 4; it++) {
        int idx = tid + it * 256; int r = idx >> 4, sg = idx & 15;
        CP_ASYNC16(sb + SM_QL + r * 272 + sg * 16,
                   Ql + (rowbase + q0 + r) * DIM + hoff + sg * 8);
    }
    asm volatile("cp.async.commit_group;");

    auto loadK = [&](int j0, uint32_t base) {
#pragma unroll
        for (int it = 0; it < 4; it++) {
            int idx = tid + it * 256; int r = idx >> 4, sg = idx & 15;
            CP_ASYNC16(base + r * 272 + sg * 16,
                       K16 + (rowbase + j0 + r) * DIM + hoff + sg * 8);
        }
        asm volatile("cp.async.commit_group;");
    };
    auto loadV = [&](int j0) {
#pragma unroll
        for (int it = 0; it < 4; it++) {
            int idx = tid + it * 256; int r = idx >> 4, sg = idx & 15;
            CP_ASYNC16(sb + SM_V + r * 272 + sg * 16,
                       V16 + (rowbase + j0 + r) * DIM + hoff + sg * 8);
        }
        asm volatile("cp.async.commit_group;");
    };

    loadK(0, sb + SM_K0);   // group: K0

    float oacc[8][4];
#pragma unroll
    for (int i = 0; i < 8; i++)
#pragma unroll
        for (int k = 0; k < 4; k++) oacc[i][k] = 0.f;
    float m0 = -1e9f, m1 = -1e9f, l0 = 0.f, l1 = 0.f;

    const int r0 = wm * 16 + (lane >> 2);
    const int r1 = r0 + 8;
    int buf = 0;

    for (int j = 0; j <= qt; j++) {
        const int j0 = j * 64;
        loadV(j0);
        if (j < qt) loadK(j0 + 64, sb + (buf ? SM_K0 : SM_K1));
        if (j < qt) asm volatile("cp.async.wait_group 2;");
        else        asm volatile("cp.async.wait_group 1;");
        __syncthreads();   // S1: Q + K[j] visible

        // ---- QK: S = Qh K^T + Ql K^T ----
        const uint32_t kb = sb + (buf ? SM_K1 : SM_K0);
        float sacc[4][4];
#pragma unroll
        for (int nf = 0; nf < 4; nf++)
#pragma unroll
            for (int e = 0; e < 4; e++) sacc[nf][e] = 0.f;

#pragma unroll
        for (int kc = 0; kc < 8; kc++) {
            uint32_t bbf[4][2];
            uint32_t kaddr = kb + (uint32_t)((wn * 32 + (lane >> 2)) * 272
                                             + kc * 32 + (lane & 3) * 4);
#pragma unroll
            for (int nf = 0; nf < 4; nf++) {
                bbf[nf][0] = lds32(kaddr + nf * 8 * 272);
                bbf[nf][1] = lds32(kaddr + nf * 8 * 272 + 16);
            }
            uint32_t qa = (uint32_t)((wm * 16 + (lane & 15)) * 272
                                     + kc * 32 + (lane >> 4) * 16);
            uint32_t ah[4], al[4];
            ldmatrix_x4(ah, sb + SM_QH + qa);
            ldmatrix_x4(al, sb + SM_QL + qa);
#pragma unroll
            for (int nf = 0; nf < 4; nf++) {
                mma_fp16(sacc[nf], ah, bbf[nf]);
                mma_fp16(sacc[nf], al, bbf[nf]);
            }
        }

        // causal mask on diagonal tile
        if (j == qt) {
#pragma unroll
            for (int nf = 0; nf < 4; nf++)
#pragma unroll
                for (int e = 0; e < 4; e++) {
                    int col = j0 + wn * 32 + nf * 8 + 2 * (lane & 3) + (e & 1);
                    int row = q0 + ((e >> 1) ? r1 : r0);
                    if (col > row) sacc[nf][e] = -1e9f;
                }
        }

        // ---- row max ----
        float mx0 = -1e30f, mx1 = -1e30f;
#pragma unroll
        for (int nf = 0; nf < 4; nf++) {
            mx0 = fmaxf(mx0, fmaxf(sacc[nf][0], sacc[nf][1]));
            mx1 = fmaxf(mx1, fmaxf(sacc[nf][2], sacc[nf][3]));
        }
        mx0 = fmaxf(mx0, __shfl_xor_sync(0xffffffffu, mx0, 1));
        mx0 = fmaxf(mx0, __shfl_xor_sync(0xffffffffu, mx0, 2));
        mx1 = fmaxf(mx1, __shfl_xor_sync(0xffffffffu, mx1, 1));
        mx1 = fmaxf(mx1, __shfl_xor_sync(0xffffffffu, mx1, 2));
        if ((lane & 3) == 0) {
            sRMax[r0 * 2 + wn] = mx0;
            sRMax[r1 * 2 + wn] = mx1;
        }
        __syncthreads();   // S2

        float nm0 = fmaxf(m0, fmaxf(sRMax[r0 * 2], sRMax[r0 * 2 + 1]));
        float nm1 = fmaxf(m1, fmaxf(sRMax[r1 * 2], sRMax[r1 * 2 + 1]));
        float alpha0 = exp2p(m0 - nm0);
        float alpha1 = exp2p(m1 - nm1);
        m0 = nm0; m1 = nm1;

        // ---- exp, pack P, partial sums ----
        float s0 = 0.f, s1 = 0.f;
        uint32_t pbase = sb + SM_P + (uint32_t)((wm * 16 + (lane >> 2)) * 144
                                                + wn * 64 + (lane & 3) * 4);
#pragma unroll
        for (int nf = 0; nf < 4; nf++) {
            float p0 = exp2p(sacc[nf][0] - m0);
            float p1 = exp2p(sacc[nf][1] - m0);
            float p2 = exp2p(sacc[nf][2] - m1);
            float p3 = exp2p(sacc[nf][3] - m1);
            s0 += p0 + p1; s1 += p2 + p3;
            __half2 hp0 = __floats2half2_rn(p0, p1);
            __half2 hp1 = __floats2half2_rn(p2, p3);
            sts32(pbase + nf * 16,              *(uint32_t*)&hp0);
            sts32(pbase + nf * 16 + 8 * 144,    *(uint32_t*)&hp1);
        }
        s0 += __shfl_xor_sync(0xffffffffu, s0, 1);
        s0 += __shfl_xor_sync(0xffffffffu, s0, 2);
        s1 += __shfl_xor_sync(0xffffffffu, s1, 1);
        s1 += __shfl_xor_sync(0xffffffffu, s1, 2);
        if ((lane & 3) == 0) {
            sRSum[r0 * 2 + wn] = s0;
            sRSum[r1 * 2 + wn] = s1;
        }

        // rescale O
#pragma unroll
        for (int nb = 0; nb < 8; nb++) {
            oacc[nb][0] *= alpha0; oacc[nb][1] *= alpha0;
            oacc[nb][2] *= alpha1; oacc[nb][3] *= alpha1;
        }

        if (j < qt) asm volatile("cp.async.wait_group 1;");
        else        asm volatile("cp.async.wait_group 0;");
        __syncthreads();   // S3: V + sP + sRSum visible

        l0 = l0 * alpha0 + sRSum[r0 * 2] + sRSum[r0 * 2 + 1];
        l1 = l1 * alpha1 + sRSum[r1 * 2] + sRSum[r1 * 2 + 1];

        // ---- PV: O += P V ----
#pragma unroll
        for (int kc = 0; kc < 4; kc++) {
            uint32_t pa[4];
            ldmatrix_x4(pa, sb + SM_P + (uint32_t)((wm * 16 + (lane & 15)) * 144
                                                   + kc * 32 + (lane >> 4) * 16));
#pragma unroll
            for (int g = 0; g < 4; g++) {
                uint32_t vb[4];
                ldmatrix_x4_trans(vb, sb + SM_V
                    + (uint32_t)((kc * 16 + (lane & 15)) * 272
                                 + (wn * 64 + g * 16 + (lane >> 4) * 8) * 2));
                mma_fp16(oacc[2 * g + 0], pa, &vb[0]);
                mma_fp16(oacc[2 * g + 1], pa, &vb[2]);
            }
        }
        __syncthreads();   // S4: sP/sV consumed before next overwrite
        buf ^= 1;
    }

    // ---- epilogue: normalize + split-fp16 store to Ah/Al ----
    float li0 = 1.f / l0, li1 = 1.f / l1;
    size_t a0 = (rowbase + q0 + r0) * DIM + hoff + wn * 64;
    size_t a1 = (rowbase + q0 + r1) * DIM + hoff + wn * 64;
#pragma unroll
    for (int nb = 0; nb < 8; nb++) {
        int c = nb * 8 + 2 * (lane & 3);
        float o0 = oacc[nb][0] * li0, o1 = oacc[nb][1] * li0;
        float o2 = oacc[nb][2] * li1, o3 = oacc[nb][3] * li1;
        __half h0 = __float2half_rn(o0), h1 = __float2half_rn(o1);
        __half h2 = __float2half_rn(o2), h3 = __float2half_rn(o3);
        *(__half2*)(OAh + a0 + c) = __halves2half2(h0, h1);
        *(__half2*)(OAh + a1 + c) = __halves2half2(h2, h3);
        *(__half2*)(OAl + a0 + c) =
            __floats2half2_rn(o0 - __half2float(h0), o1 - __half2float(h1));
        *(__half2*)(OAl + a1 + c) =
            __floats2half2_rn(o2 - __half2float(h2), o3 - __half2float(h3));
    }
}

// ---------------- launch ----------------
extern "C" void kernel_launch(void* const* d_in, const int* in_sizes, int n_in,
                              void* d_out, int out_size)
{
    const float* enc  = (const float*)d_in[0];
    const float* dec  = (const float*)d_in[1];
    const float* W_kv = (const float*)d_in[2];
    const float* b_kv = (const float*)d_in[3];
    const float* W_q  = (const float*)d_in[4];
    const float* b_q  = (const float*)d_in[5];
    const float* W_o  = (const float*)d_in[6];
    const float* b_o  = (const float*)d_in[7];
    float* out = (float*)d_out;

    __half *p_Ah, *p_Al, *p_Wh, *p_K, *p_V, *p_Qh, *p_Ql;
    cudaGetSymbolAddress((void**)&p_Ah, g_Ah);
    cudaGetSymbolAddress((void**)&p_Al, g_Al);
    cudaGetSymbolAddress((void**)&p_Wh, g_Wh);
    cudaGetSymbolAddress((void**)&p_K,  g_K16);
    cudaGetSymbolAddress((void**)&p_V,  g_V16);
    cudaGetSymbolAddress((void**)&p_Qh, g_Qh);
    cudaGetSymbolAddress((void**)&p_Ql, g_Ql);

    cudaFuncSetAttribute(gemm_tc_kernel<0>, cudaFuncAttributeMaxDynamicSharedMemorySize, GEMM_SMEM);
    cudaFuncSetAttribute(gemm_tc_kernel<1>, cudaFuncAttributeMaxDynamicSharedMemorySize, GEMM_SMEM);
    cudaFuncSetAttribute(gemm_tc_kernel<2>, cudaFuncAttributeMaxDynamicSharedMemorySize, GEMM_SMEM);
    cudaFuncSetAttribute(attn_tc_kernel, cudaFuncAttributeMaxDynamicSharedMemorySize, ATT_SMEM);

    const int nA4 = MROWS * DIM / 4;

    // GEMM 1: kv projection -> K16/V16 fp16
    conv_w_kernel<<<dim3(KVDIM / 32, DIM / 32), dim3(32, 8)>>>(W_kv, p_Wh, DIM, KVDIM);
    conv_split_kernel<<<(nA4 + 255) / 256, 256>>>(enc, p_Ah, p_Al, nA4);
    gemm_tc_kernel<1><<<dim3(KVDIM / 128, MROWS / 128), 256, GEMM_SMEM>>>(
        p_Ah, p_Al, p_Wh, b_kv, p_K, p_V, KVDIM);

    // GEMM 2: q projection -> scaled split fp16 Qh/Ql
    conv_w_kernel<<<dim3(DIM / 32, DIM / 32), dim3(32, 8)>>>(W_q, p_Wh, DIM, DIM);
    conv_split_kernel<<<(nA4 + 255) / 256, 256>>>(dec, p_Ah, p_Al, nA4);
    gemm_tc_kernel<2><<<dim3(DIM / 128, MROWS / 128), 256, GEMM_SMEM>>>(
        p_Ah, p_Al, p_Wh, b_q, p_Qh, p_Ql, DIM);

    // attention -> split fp16 into Ah/Al (input of GEMM 3)
    attn_tc_kernel<<<dim3(TSEQ / 64, BATCH * NHEAD), 256, ATT_SMEM>>>(
        p_Qh, p_Ql, p_K, p_V, p_Ah, p_Al);

    // GEMM 3: output projection (fp32 out)
    conv_w_kernel<<<dim3(DIM / 32, DIM / 32), dim3(32, 8)>>>(W_o, p_Wh, DIM, DIM);
    gemm_tc_kernel<0><<<dim3(DIM / 128, MROWS / 128), 256, GEMM_SMEM>>>(
        p_Ah, p_Al, p_Wh, b_o, out, nullptr, DIM);
}

// round 6
// speedup vs baseline: 4.5062x; 1.1150x over previous
#include <cuda_runtime.h>
#include <cuda_fp16.h>
#include <cstdint>

#define TSEQ   2048
#define BATCH  4
#define NHEAD  16
#define HD     128
#define DIM    2048
#define MROWS  (BATCH * TSEQ)   // 8192
#define KVDIM  (2 * DIM)        // 4096

// ---------------- scratch (allocation-free: __device__ globals) ----------------
__device__ __half g_Ah [(size_t)MROWS * DIM];
__device__ __half g_Al [(size_t)MROWS * DIM];
__device__ __half g_Wh [(size_t)KVDIM * DIM];
__device__ __half g_K16[(size_t)MROWS * DIM];
__device__ __half g_V16[(size_t)MROWS * DIM];
__device__ __half g_Qh [(size_t)MROWS * DIM];
__device__ __half g_Ql [(size_t)MROWS * DIM];

// ---------------- helpers ----------------
__device__ __forceinline__ uint32_t smem_u32(const void* p) {
    uint32_t a;
    asm("{ .reg .u64 t; cvta.to.shared.u64 t, %1; cvt.u32.u64 %0, t; }"
        : "=r"(a) : "l"(p));
    return a;
}
#define CP_ASYNC16(dst, src) \
    asm volatile("cp.async.cg.shared.global [%0], [%1], 16;" :: "r"(dst), "l"(src))

__device__ __forceinline__ void ldmatrix_x4(uint32_t* r, uint32_t addr) {
    asm volatile("ldmatrix.sync.aligned.m8n8.x4.shared.b16 {%0,%1,%2,%3}, [%4];"
                 : "=r"(r[0]), "=r"(r[1]), "=r"(r[2]), "=r"(r[3]) : "r"(addr));
}
__device__ __forceinline__ void ldmatrix_x4_trans(uint32_t* r, uint32_t addr) {
    asm volatile("ldmatrix.sync.aligned.m8n8.x4.trans.shared.b16 {%0,%1,%2,%3}, [%4];"
                 : "=r"(r[0]), "=r"(r[1]), "=r"(r[2]), "=r"(r[3]) : "r"(addr));
}
__device__ __forceinline__ void sts32(uint32_t a, uint32_t v) {
    asm volatile("st.shared.b32 [%0], %1;" :: "r"(a), "r"(v));
}
__device__ __forceinline__ void mma_fp16(float* d, const uint32_t* a, const uint32_t* b) {
    asm volatile(
        "mma.sync.aligned.m16n8k16.row.col.f32.f16.f16.f32 "
        "{%0,%1,%2,%3}, {%4,%5,%6,%7}, {%8,%9}, {%0,%1,%2,%3};"
        : "+f"(d[0]), "+f"(d[1]), "+f"(d[2]), "+f"(d[3])
        : "r"(a[0]), "r"(a[1]), "r"(a[2]), "r"(a[3]), "r"(b[0]), "r"(b[1]));
}

// fast exp2 on FMA pipe (t <= ~0)
__device__ __forceinline__ float exp2p(float t) {
    t = fmaxf(t, -126.f);
    float fi = floorf(t);
    float x = t - fi - 0.5f;
    float p = 0.001885630f;
    p = fmaf(p, x, 0.013602145f);
    p = fmaf(p, x, 0.078494717f);
    p = fmaf(p, x, 0.339731669f);
    p = fmaf(p, x, 0.980258143f);
    p = fmaf(p, x, 1.414213562f);
    int e = (int)fi;
    return __int_as_float(__float_as_int(p) + (e << 23));
}

// B-operand address for ldmatrix_x4 covering 2 n-fragments (16 n rows x 16 k):
// lane>>3 selects tile: bit0 -> +16B in k, bit1 -> +8 rows in n.
__device__ __forceinline__ uint32_t bfrag_addr(uint32_t base, int lane,
                                               int nrow0, int stride, int kbyte) {
    int g = lane >> 3;
    int r = lane & 7;
    return base + (uint32_t)((nrow0 + ((g >> 1) << 3) + r) * stride
                             + kbyte + ((g & 1) << 4));
}

// ---------------- conversion kernels ----------------
__global__ __launch_bounds__(256) void conv_split_kernel(
    const float* __restrict__ x, __half* __restrict__ h,
    __half* __restrict__ l, int n4)
{
    int i = blockIdx.x * 256 + threadIdx.x;
    if (i >= n4) return;
    float4 v = ((const float4*)x)[i];
    float a[4] = {v.x, v.y, v.z, v.w};
    __half hh[4], ll[4];
#pragma unroll
    for (int k = 0; k < 4; k++) {
        hh[k] = __float2half(a[k]);
        ll[k] = __float2half(a[k] - __half2float(hh[k]));
    }
    __half2* hp = (__half2*)(h + (size_t)i * 4);
    __half2* lp = (__half2*)(l + (size_t)i * 4);
    hp[0] = __half2{hh[0], hh[1]};
    hp[1] = __half2{hh[2], hh[3]};
    lp[0] = __half2{ll[0], ll[1]};
    lp[1] = __half2{ll[2], ll[3]};
}

__global__ __launch_bounds__(256) void conv_w_kernel(
    const float* __restrict__ W, __half* __restrict__ Wh, int K, int N)
{
    __shared__ float t[32][33];
    int n0 = blockIdx.x * 32, k0 = blockIdx.y * 32;
    int tx = threadIdx.x, ty = threadIdx.y;
#pragma unroll
    for (int r = 0; r < 4; r++)
        t[ty + 8 * r][tx] = W[(size_t)(k0 + ty + 8 * r) * N + n0 + tx];
    __syncthreads();
#pragma unroll
    for (int r = 0; r < 4; r++) {
        float v = t[tx][ty + 8 * r];
        Wh[(size_t)(n0 + ty + 8 * r) * K + k0 + tx] = __float2half(v);
    }
}

// ---------------- mma.sync GEMM (fp16, 2-pass split), templated epilogue ----------------
#define BKG      64
#define ASTRIDE  72
#define ROWB     (ASTRIDE * 2)            // 144 B
#define ATILE_B  (128 * ROWB)
#define BUF_B    (2 * ATILE_B)
#define GEMM_SMEM (2 * BUF_B)             // 73728 -> 2 CTAs/SM
#define NCH 64

template<int MODE>
__global__ __launch_bounds__(256, 2) void gemm_tc_kernel(
    const __half* __restrict__ Ah, const __half* __restrict__ Al,
    const __half* __restrict__ Wh,
    const float* __restrict__ bias, void* outA, void* outB, int N)
{
    extern __shared__ char smem[];
    const uint32_t sbase = smem_u32(smem);
    const int tid  = threadIdx.x;
    const int wid  = tid >> 5;
    const int lane = tid & 31;
    const int wm   = wid & 1;
    const int wn   = wid >> 1;
    const int bm   = blockIdx.y * 128;
    const int bn   = blockIdx.x * 128;

    const __half* APs[2] = {Ah, Al};

    float acc[4][4][4];
#pragma unroll
    for (int i = 0; i < 4; i++)
#pragma unroll
        for (int j = 0; j < 4; j++)
#pragma unroll
            for (int k = 0; k < 4; k++) acc[i][j][k] = 0.f;

    const uint32_t a_lane_off = (uint32_t)((lane & 15) * ROWB + ((lane >> 4) << 3) * 2);
    const uint32_t a_warp_base = (uint32_t)(wm * 64) * ROWB;

    auto load_chunk = [&](int ci, int buf) {
        const int pass = ci >> 5;
        const int k0 = (ci & 31) * BKG;
        const __half* Ap = APs[pass];
        const uint32_t base = sbase + (uint32_t)buf * BUF_B;
#pragma unroll
        for (int j = 0; j < 8; j++) {
            int c = j * 256 + tid;
            int row = (c >> 3) & 127;
            int c16 = c & 7;
            uint32_t dst;
            const __half* g;
            if (c < 1024) {
                dst = base + (uint32_t)(row * ROWB + c16 * 16);
                g = Ap + (size_t)(bm + row) * DIM + k0 + c16 * 8;
            } else {
                dst = base + (uint32_t)(ATILE_B + row * ROWB + c16 * 16);
                g = Wh + (size_t)(bn + row) * DIM + k0 + c16 * 8;
            }
            CP_ASYNC16(dst, g);
        }
        asm volatile("cp.async.commit_group;");
    };

    load_chunk(0, 0);

    for (int i = 0; i < NCH; i++) {
        const int b = i & 1;
        const bool has_next = (i + 1 < NCH);
        if (has_next) load_chunk(i + 1, b ^ 1);
        if (has_next) asm volatile("cp.async.wait_group 1;");
        else          asm volatile("cp.async.wait_group 0;");
        __syncthreads();

        const uint32_t abuf = sbase + (uint32_t)b * BUF_B;
        const uint32_t bbuf = abuf + ATILE_B;
#pragma unroll
        for (int ks = 0; ks < 4; ks++) {
            uint32_t afrag[4][4];
#pragma unroll
            for (int mf = 0; mf < 4; mf++)
                ldmatrix_x4(afrag[mf],
                            abuf + a_warp_base + (uint32_t)(mf * 16 * ROWB)
                                 + (uint32_t)(ks * 32) + a_lane_off);
            uint32_t bfrag[4][2];
#pragma unroll
            for (int p = 0; p < 2; p++) {
                uint32_t r4[4];
                ldmatrix_x4(r4, bfrag_addr(bbuf, lane, wn * 32 + p * 16,
                                           ROWB, ks * 32));
                bfrag[2 * p + 0][0] = r4[0]; bfrag[2 * p + 0][1] = r4[1];
                bfrag[2 * p + 1][0] = r4[2]; bfrag[2 * p + 1][1] = r4[3];
            }
#pragma unroll
            for (int mf = 0; mf < 4; mf++)
#pragma unroll
                for (int nf = 0; nf < 4; nf++)
                    mma_fp16(acc[mf][nf], afrag[mf], bfrag[nf]);
        }
        __syncthreads();
    }

    // ---- epilogue ----
    const float CSCL = (float)(0.08838834764831845 * 1.4426950408889634);
    float2 bfr[4];
#pragma unroll
    for (int nf = 0; nf < 4; nf++) {
        int col = bn + wn * 32 + nf * 8 + (lane & 3) * 2;
        bfr[nf].x = __ldg(bias + col);
        bfr[nf].y = __ldg(bias + col + 1);
    }
#pragma unroll
    for (int mf = 0; mf < 4; mf++) {
#pragma unroll
        for (int h8 = 0; h8 < 2; h8++) {
            int row = bm + wm * 64 + mf * 16 + (lane >> 2) + h8 * 8;
#pragma unroll
            for (int nf = 0; nf < 4; nf++) {
                float vx = acc[mf][nf][2 * h8 + 0] + bfr[nf].x;
                float vy = acc[mf][nf][2 * h8 + 1] + bfr[nf].y;
                int coff = wn * 32 + nf * 8 + (lane & 3) * 2;
                if (MODE == 0) {
                    float* C = (float*)outA;
                    float2 o; o.x = vx; o.y = vy;
                    *(float2*)(C + (size_t)row * N + bn + coff) = o;
                } else if (MODE == 1) {
                    __half* dst = (bn < DIM) ? (__half*)outA : (__half*)outB;
                    int cb = (bn & (DIM - 1)) + coff;
                    *(__half2*)(dst + (size_t)row * DIM + cb) =
                        __floats2half2_rn(vx, vy);
                } else {
                    float qx = vx * CSCL, qy = vy * CSCL;
                    __half hx = __float2half_rn(qx), hy = __float2half_rn(qy);
                    size_t adr = (size_t)row * DIM + bn + coff;
                    *(__half2*)((__half*)outA + adr) = __halves2half2(hx, hy);
                    *(__half2*)((__half*)outB + adr) =
                        __floats2half2_rn(qx - __half2float(hx), qy - __half2float(hy));
                }
            }
        }
    }
}

// ---------------- fp16 tensor-core flash attention ----------------
#define SM_QH   0
#define SM_QL   17408
#define SM_K0   34816
#define SM_K1   52224
#define SM_V    69632
#define SM_P    87040
#define SM_RMAX 96256
#define SM_RSUM 96768
#define ATT_SMEM 97280

__global__ __launch_bounds__(256, 2) void attn_tc_kernel(
    const __half* __restrict__ Qh, const __half* __restrict__ Ql,
    const __half* __restrict__ K16, const __half* __restrict__ V16,
    __half* __restrict__ OAh, __half* __restrict__ OAl)
{
    extern __shared__ char smem[];
    const uint32_t sb = smem_u32(smem);
    const int tid = threadIdx.x, lane = tid & 31, wid = tid >> 5;
    const int wm = wid & 3, wn = wid >> 2;
    const int qt = (int)gridDim.x - 1 - (int)blockIdx.x;
    const int bh = blockIdx.y, bb = bh >> 4, hh = bh & 15;
    const int q0 = qt * 64;
    const size_t rowbase = (size_t)bb * TSEQ;
    const int hoff = hh * HD;

    float* sRMax = (float*)(smem + SM_RMAX);
    float* sRSum = (float*)(smem + SM_RSUM);

#pragma unroll
    for (int it = 0; it < 4; it++) {
        int idx = tid + it * 256; int r = idx >> 4, sg = idx & 15;
        CP_ASYNC16(sb + SM_QH + r * 272 + sg * 16,
                   Qh + (rowbase + q0 + r) * DIM + hoff + sg * 8);
    }
#pragma unroll
    for (int it = 0; it < 4; it++) {
        int idx = tid + it * 256; int r = idx >> 4, sg = idx & 15;
        CP_ASYNC16(sb + SM_QL + r * 272 + sg * 16,
                   Ql + (rowbase + q0 + r) * DIM + hoff + sg * 8);
    }
    asm volatile("cp.async.commit_group;");

    auto loadK = [&](int j0, uint32_t base) {
#pragma unroll
        for (int it = 0; it < 4; it++) {
            int idx = tid + it * 256; int r = idx >> 4, sg = idx & 15;
            CP_ASYNC16(base + r * 272 + sg * 16,
                       K16 + (rowbase + j0 + r) * DIM + hoff + sg * 8);
        }
        asm volatile("cp.async.commit_group;");
    };
    auto loadV = [&](int j0) {
#pragma unroll
        for (int it = 0; it < 4; it++) {
            int idx = tid + it * 256; int r = idx >> 4, sg = idx & 15;
            CP_ASYNC16(sb + SM_V + r * 272 + sg * 16,
                       V16 + (rowbase + j0 + r) * DIM + hoff + sg * 8);
        }
        asm volatile("cp.async.commit_group;");
    };

    loadK(0, sb + SM_K0);

    float oacc[8][4];
#pragma unroll
    for (int i = 0; i < 8; i++)
#pragma unroll
        for (int k = 0; k < 4; k++) oacc[i][k] = 0.f;
    float m0 = -1e9f, m1 = -1e9f, l0 = 0.f, l1 = 0.f;

    const int r0 = wm * 16 + (lane >> 2);
    const int r1 = r0 + 8;
    int buf = 0;

    for (int j = 0; j <= qt; j++) {
        const int j0 = j * 64;
        loadV(j0);
        if (j < qt) loadK(j0 + 64, sb + (buf ? SM_K0 : SM_K1));
        if (j < qt) asm volatile("cp.async.wait_group 2;");
        else        asm volatile("cp.async.wait_group 1;");
        __syncthreads();   // S1

        const uint32_t kb = sb + (buf ? SM_K1 : SM_K0);
        float sacc[4][4];
#pragma unroll
        for (int nf = 0; nf < 4; nf++)
#pragma unroll
            for (int e = 0; e < 4; e++) sacc[nf][e] = 0.f;

#pragma unroll
        for (int kc = 0; kc < 8; kc++) {
            uint32_t bbf[4][2];
#pragma unroll
            for (int p = 0; p < 2; p++) {
                uint32_t r4[4];
                ldmatrix_x4(r4, bfrag_addr(kb, lane, wn * 32 + p * 16,
                                           272, kc * 32));
                bbf[2 * p + 0][0] = r4[0]; bbf[2 * p + 0][1] = r4[1];
                bbf[2 * p + 1][0] = r4[2]; bbf[2 * p + 1][1] = r4[3];
            }
            uint32_t qa = (uint32_t)((wm * 16 + (lane & 15)) * 272
                                     + kc * 32 + (lane >> 4) * 16);
            uint32_t ah[4], al[4];
            ldmatrix_x4(ah, sb + SM_QH + qa);
            ldmatrix_x4(al, sb + SM_QL + qa);
#pragma unroll
            for (int nf = 0; nf < 4; nf++) {
                mma_fp16(sacc[nf], ah, bbf[nf]);
                mma_fp16(sacc[nf], al, bbf[nf]);
            }
        }

        if (j == qt) {
#pragma unroll
            for (int nf = 0; nf < 4; nf++)
#pragma unroll
                for (int e = 0; e < 4; e++) {
                    int col = j0 + wn * 32 + nf * 8 + 2 * (lane & 3) + (e & 1);
                    int row = q0 + ((e >> 1) ? r1 : r0);
                    if (col > row) sacc[nf][e] = -1e9f;
                }
        }

        float mx0 = -1e30f, mx1 = -1e30f;
#pragma unroll
        for (int nf = 0; nf < 4; nf++) {
            mx0 = fmaxf(mx0, fmaxf(sacc[nf][0], sacc[nf][1]));
            mx1 = fmaxf(mx1, fmaxf(sacc[nf][2], sacc[nf][3]));
        }
        mx0 = fmaxf(mx0, __shfl_xor_sync(0xffffffffu, mx0, 1));
        mx0 = fmaxf(mx0, __shfl_xor_sync(0xffffffffu, mx0, 2));
        mx1 = fmaxf(mx1, __shfl_xor_sync(0xffffffffu, mx1, 1));
        mx1 = fmaxf(mx1, __shfl_xor_sync(0xffffffffu, mx1, 2));
        if ((lane & 3) == 0) {
            sRMax[r0 * 2 + wn] = mx0;
            sRMax[r1 * 2 + wn] = mx1;
        }
        __syncthreads();   // S2

        float nm0 = fmaxf(m0, fmaxf(sRMax[r0 * 2], sRMax[r0 * 2 + 1]));
        float nm1 = fmaxf(m1, fmaxf(sRMax[r1 * 2], sRMax[r1 * 2 + 1]));
        float alpha0 = exp2p(m0 - nm0);
        float alpha1 = exp2p(m1 - nm1);
        m0 = nm0; m1 = nm1;

        float s0 = 0.f, s1 = 0.f;
        uint32_t pbase = sb + SM_P + (uint32_t)((wm * 16 + (lane >> 2)) * 144
                                                + wn * 64 + (lane & 3) * 4);
#pragma unroll
        for (int nf = 0; nf < 4; nf++) {
            float p0 = exp2p(sacc[nf][0] - m0);
            float p1 = exp2p(sacc[nf][1] - m0);
            float p2 = exp2p(sacc[nf][2] - m1);
            float p3 = exp2p(sacc[nf][3] - m1);
            s0 += p0 + p1; s1 += p2 + p3;
            __half2 hp0 = __floats2half2_rn(p0, p1);
            __half2 hp1 = __floats2half2_rn(p2, p3);
            sts32(pbase + nf * 16,              *(uint32_t*)&hp0);
            sts32(pbase + nf * 16 + 8 * 144,    *(uint32_t*)&hp1);
        }
        s0 += __shfl_xor_sync(0xffffffffu, s0, 1);
        s0 += __shfl_xor_sync(0xffffffffu, s0, 2);
        s1 += __shfl_xor_sync(0xffffffffu, s1, 1);
        s1 += __shfl_xor_sync(0xffffffffu, s1, 2);
        if ((lane & 3) == 0) {
            sRSum[r0 * 2 + wn] = s0;
            sRSum[r1 * 2 + wn] = s1;
        }

#pragma unroll
        for (int nb = 0; nb < 8; nb++) {
            oacc[nb][0] *= alpha0; oacc[nb][1] *= alpha0;
            oacc[nb][2] *= alpha1; oacc[nb][3] *= alpha1;
        }

        if (j < qt) asm volatile("cp.async.wait_group 1;");
        else        asm volatile("cp.async.wait_group 0;");
        __syncthreads();   // S3

        l0 = l0 * alpha0 + sRSum[r0 * 2] + sRSum[r0 * 2 + 1];
        l1 = l1 * alpha1 + sRSum[r1 * 2] + sRSum[r1 * 2 + 1];

#pragma unroll
        for (int kc = 0; kc < 4; kc++) {
            uint32_t pa[4];
            ldmatrix_x4(pa, sb + SM_P + (uint32_t)((wm * 16 + (lane & 15)) * 144
                                                   + kc * 32 + (lane >> 4) * 16));
#pragma unroll
            for (int g = 0; g < 4; g++) {
                uint32_t vb[4];
                ldmatrix_x4_trans(vb, sb + SM_V
                    + (uint32_t)((kc * 16 + (lane & 15)) * 272
                                 + (wn * 64 + g * 16 + (lane >> 4) * 8) * 2));
                mma_fp16(oacc[2 * g + 0], pa, &vb[0]);
                mma_fp16(oacc[2 * g + 1], pa, &vb[2]);
            }
        }
        __syncthreads();   // S4
        buf ^= 1;
    }

    float li0 = 1.f / l0, li1 = 1.f / l1;
    size_t a0 = (rowbase + q0 + r0) * DIM + hoff + wn * 64;
    size_t a1 = (rowbase + q0 + r1) * DIM + hoff + wn * 64;
#pragma unroll
    for (int nb = 0; nb < 8; nb++) {
        int c = nb * 8 + 2 * (lane & 3);
        float o0 = oacc[nb][0] * li0, o1 = oacc[nb][1] * li0;
        float o2 = oacc[nb][2] * li1, o3 = oacc[nb][3] * li1;
        __half h0 = __float2half_rn(o0), h1 = __float2half_rn(o1);
        __half h2 = __float2half_rn(o2), h3 = __float2half_rn(o3);
        *(__half2*)(OAh + a0 + c) = __halves2half2(h0, h1);
        *(__half2*)(OAh + a1 + c) = __halves2half2(h2, h3);
        *(__half2*)(OAl + a0 + c) =
            __floats2half2_rn(o0 - __half2float(h0), o1 - __half2float(h1));
        *(__half2*)(OAl + a1 + c) =
            __floats2half2_rn(o2 - __half2float(h2), o3 - __half2float(h3));
    }
}

// ---------------- launch ----------------
extern "C" void kernel_launch(void* const* d_in, const int* in_sizes, int n_in,
                              void* d_out, int out_size)
{
    const float* enc  = (const float*)d_in[0];
    const float* dec  = (const float*)d_in[1];
    const float* W_kv = (const float*)d_in[2];
    const float* b_kv = (const float*)d_in[3];
    const float* W_q  = (const float*)d_in[4];
    const float* b_q  = (const float*)d_in[5];
    const float* W_o  = (const float*)d_in[6];
    const float* b_o  = (const float*)d_in[7];
    float* out = (float*)d_out;

    __half *p_Ah, *p_Al, *p_Wh, *p_K, *p_V, *p_Qh, *p_Ql;
    cudaGetSymbolAddress((void**)&p_Ah, g_Ah);
    cudaGetSymbolAddress((void**)&p_Al, g_Al);
    cudaGetSymbolAddress((void**)&p_Wh, g_Wh);
    cudaGetSymbolAddress((void**)&p_K,  g_K16);
    cudaGetSymbolAddress((void**)&p_V,  g_V16);
    cudaGetSymbolAddress((void**)&p_Qh, g_Qh);
    cudaGetSymbolAddress((void**)&p_Ql, g_Ql);

    cudaFuncSetAttribute(gemm_tc_kernel<0>, cudaFuncAttributeMaxDynamicSharedMemorySize, GEMM_SMEM);
    cudaFuncSetAttribute(gemm_tc_kernel<1>, cudaFuncAttributeMaxDynamicSharedMemorySize, GEMM_SMEM);
    cudaFuncSetAttribute(gemm_tc_kernel<2>, cudaFuncAttributeMaxDynamicSharedMemorySize, GEMM_SMEM);
    cudaFuncSetAttribute(attn_tc_kernel, cudaFuncAttributeMaxDynamicSharedMemorySize, ATT_SMEM);

    const int nA4 = MROWS * DIM / 4;

    // GEMM 1: kv projection -> K16/V16 fp16
    conv_w_kernel<<<dim3(KVDIM / 32, DIM / 32), dim3(32, 8)>>>(W_kv, p_Wh, DIM, KVDIM);
    conv_split_kernel<<<(nA4 + 255) / 256, 256>>>(enc, p_Ah, p_Al, nA4);
    gemm_tc_kernel<1><<<dim3(KVDIM / 128, MROWS / 128), 256, GEMM_SMEM>>>(
        p_Ah, p_Al, p_Wh, b_kv, p_K, p_V, KVDIM);

    // GEMM 2: q projection -> scaled split fp16 Qh/Ql
    conv_w_kernel<<<dim3(DIM / 32, DIM / 32), dim3(32, 8)>>>(W_q, p_Wh, DIM, DIM);
    conv_split_kernel<<<(nA4 + 255) / 256, 256>>>(dec, p_Ah, p_Al, nA4);
    gemm_tc_kernel<2><<<dim3(DIM / 128, MROWS / 128), 256, GEMM_SMEM>>>(
        p_Ah, p_Al, p_Wh, b_q, p_Qh, p_Ql, DIM);

    // attention -> split fp16 into Ah/Al
    attn_tc_kernel<<<dim3(TSEQ / 64, BATCH * NHEAD), 256, ATT_SMEM>>>(
        p_Qh, p_Ql, p_K, p_V, p_Ah, p_Al);

    // GEMM 3: output projection (fp32 out)
    conv_w_kernel<<<dim3(DIM / 32, DIM / 32), dim3(32, 8)>>>(W_o, p_Wh, DIM, DIM);
    gemm_tc_kernel<0><<<dim3(DIM / 128, MROWS / 128), 256, GEMM_SMEM>>>(
        p_Ah, p_Al, p_Wh, b_o, out, nullptr, DIM);
}

// round 8
// speedup vs baseline: 6.4219x; 1.4251x over previous
#include <cuda_runtime.h>
#include <cuda_fp16.h>
#include <cstdint>

#define TSEQ   2048
#define BATCH  4
#define NHEAD  16
#define HD     128
#define DIM    2048
#define MROWS  (BATCH * TSEQ)   // 8192
#define KVDIM  (2 * DIM)        // 4096

// ---------------- scratch (allocation-free: __device__ globals) ----------------
__device__ __half g_Ah [(size_t)MROWS * DIM];
__device__ __half g_Al [(size_t)MROWS * DIM];
__device__ __half g_Wh [(size_t)KVDIM * DIM];
__device__ __half g_K16[(size_t)MROWS * DIM];
__device__ __half g_V16[(size_t)MROWS * DIM];
__device__ __half g_Qh [(size_t)MROWS * DIM];

// ---------------- helpers ----------------
__device__ __forceinline__ uint32_t smem_u32(const void* p) {
    uint32_t a;
    asm("{ .reg .u64 t; cvta.to.shared.u64 t, %1; cvt.u32.u64 %0, t; }"
        : "=r"(a) : "l"(p));
    return a;
}
#define CP_ASYNC16(dst, src) \
    asm volatile("cp.async.cg.shared.global [%0], [%1], 16;" :: "r"(dst), "l"(src))

__device__ __forceinline__ void ldmatrix_x4(uint32_t* r, uint32_t addr) {
    asm volatile("ldmatrix.sync.aligned.m8n8.x4.shared.b16 {%0,%1,%2,%3}, [%4];"
                 : "=r"(r[0]), "=r"(r[1]), "=r"(r[2]), "=r"(r[3]) : "r"(addr));
}
__device__ __forceinline__ void ldmatrix_x4_trans(uint32_t* r, uint32_t addr) {
    asm volatile("ldmatrix.sync.aligned.m8n8.x4.trans.shared.b16 {%0,%1,%2,%3}, [%4];"
                 : "=r"(r[0]), "=r"(r[1]), "=r"(r[2]), "=r"(r[3]) : "r"(addr));
}
__device__ __forceinline__ void sts32(uint32_t a, uint32_t v) {
    asm volatile("st.shared.b32 [%0], %1;" :: "r"(a), "r"(v));
}
__device__ __forceinline__ void mma_fp16(float* d, const uint32_t* a, const uint32_t* b) {
    asm volatile(
        "mma.sync.aligned.m16n8k16.row.col.f32.f16.f16.f32 "
        "{%0,%1,%2,%3}, {%4,%5,%6,%7}, {%8,%9}, {%0,%1,%2,%3};"
        : "+f"(d[0]), "+f"(d[1]), "+f"(d[2]), "+f"(d[3])
        : "r"(a[0]), "r"(a[1]), "r"(a[2]), "r"(a[3]), "r"(b[0]), "r"(b[1]));
}

// fast exp2 on FMA pipe (t <= ~0)
__device__ __forceinline__ float exp2p(float t) {
    t = fmaxf(t, -126.f);
    float fi = floorf(t);
    float x = t - fi - 0.5f;
    float p = 0.001885630f;
    p = fmaf(p, x, 0.013602145f);
    p = fmaf(p, x, 0.078494717f);
    p = fmaf(p, x, 0.339731669f);
    p = fmaf(p, x, 0.980258143f);
    p = fmaf(p, x, 1.414213562f);
    int e = (int)fi;
    return __int_as_float(__float_as_int(p) + (e << 23));
}

__device__ __forceinline__ uint32_t bfrag_addr(uint32_t base, int lane,
                                               int nrow0, int stride, int kbyte) {
    int g = lane >> 3;
    int r = lane & 7;
    return base + (uint32_t)((nrow0 + ((g >> 1) << 3) + r) * stride
                             + kbyte + ((g & 1) << 4));
}

// ---------------- conversion kernels ----------------
// fp32 -> fp16 (hi only)
__global__ __launch_bounds__(256) void conv_h_kernel(
    const float* __restrict__ x, __half* __restrict__ h, int n4)
{
    int i = blockIdx.x * 256 + threadIdx.x;
    if (i >= n4) return;
    float4 v = ((const float4*)x)[i];
    __half2* hp = (__half2*)(h + (size_t)i * 4);
    hp[0] = __floats2half2_rn(v.x, v.y);
    hp[1] = __floats2half2_rn(v.z, v.w);
}

__global__ __launch_bounds__(256) void conv_w_kernel(
    const float* __restrict__ W, __half* __restrict__ Wh, int K, int N)
{
    __shared__ float t[32][33];
    int n0 = blockIdx.x * 32, k0 = blockIdx.y * 32;
    int tx = threadIdx.x, ty = threadIdx.y;
#pragma unroll
    for (int r = 0; r < 4; r++)
        t[ty + 8 * r][tx] = W[(size_t)(k0 + ty + 8 * r) * N + n0 + tx];
    __syncthreads();
#pragma unroll
    for (int r = 0; r < 4; r++) {
        float v = t[tx][ty + 8 * r];
        Wh[(size_t)(n0 + ty + 8 * r) * K + k0 + tx] = __float2half(v);
    }
}

// ---------------- mma.sync GEMM (fp16), templated epilogue + pass count ----------------
// MODE 0: fp32 C = acc + bias           (outA = float* C)
// MODE 1: fp16 K/V split by column      (outA = K16, outB = V16)
// MODE 2: fp16 scaled q                 (outA = Qh)
#define BKG      64
#define ASTRIDE  72
#define ROWB     (ASTRIDE * 2)            // 144 B
#define ATILE_B  (128 * ROWB)
#define BUF_B    (2 * ATILE_B)
#define GEMM_SMEM (2 * BUF_B)             // 73728 -> 2 CTAs/SM

template<int MODE, int PASSES>
__global__ __launch_bounds__(256, 2) void gemm_tc_kernel(
    const __half* __restrict__ Ah, const __half* __restrict__ Al,
    const __half* __restrict__ Wh,
    const float* __restrict__ bias, void* outA, void* outB, int N)
{
    extern __shared__ char smem[];
    const uint32_t sbase = smem_u32(smem);
    const int tid  = threadIdx.x;
    const int wid  = tid >> 5;
    const int lane = tid & 31;
    const int wm   = wid & 1;
    const int wn   = wid >> 1;
    const int bm   = blockIdx.y * 128;
    const int bn   = blockIdx.x * 128;
    const int NCH  = PASSES * 32;

    float acc[4][4][4];
#pragma unroll
    for (int i = 0; i < 4; i++)
#pragma unroll
        for (int j = 0; j < 4; j++)
#pragma unroll
            for (int k = 0; k < 4; k++) acc[i][j][k] = 0.f;

    const uint32_t a_lane_off = (uint32_t)((lane & 15) * ROWB + ((lane >> 4) << 3) * 2);
    const uint32_t a_warp_base = (uint32_t)(wm * 64) * ROWB;

    auto load_chunk = [&](int ci, int buf) {
        const int pass = ci >> 5;
        const int k0 = (ci & 31) * BKG;
        const __half* Ap = (PASSES == 2 && pass) ? Al : Ah;
        const uint32_t base = sbase + (uint32_t)buf * BUF_B;
#pragma unroll
        for (int j = 0; j < 8; j++) {
            int c = j * 256 + tid;
            int row = (c >> 3) & 127;
            int c16 = c & 7;
            uint32_t dst;
            const __half* g;
            if (c < 1024) {
                dst = base + (uint32_t)(row * ROWB + c16 * 16);
                g = Ap + (size_t)(bm + row) * DIM + k0 + c16 * 8;
            } else {
                dst = base + (uint32_t)(ATILE_B + row * ROWB + c16 * 16);
                g = Wh + (size_t)(bn + row) * DIM + k0 + c16 * 8;
            }
            CP_ASYNC16(dst, g);
        }
        asm volatile("cp.async.commit_group;");
    };

    load_chunk(0, 0);

    for (int i = 0; i < NCH; i++) {
        const int b = i & 1;
        const bool has_next = (i + 1 < NCH);
        if (has_next) load_chunk(i + 1, b ^ 1);
        if (has_next) asm volatile("cp.async.wait_group 1;");
        else          asm volatile("cp.async.wait_group 0;");
        __syncthreads();

        const uint32_t abuf = sbase + (uint32_t)b * BUF_B;
        const uint32_t bbuf = abuf + ATILE_B;
#pragma unroll
        for (int ks = 0; ks < 4; ks++) {
            uint32_t afrag[4][4];
#pragma unroll
            for (int mf = 0; mf < 4; mf++)
                ldmatrix_x4(afrag[mf],
                            abuf + a_warp_base + (uint32_t)(mf * 16 * ROWB)
                                 + (uint32_t)(ks * 32) + a_lane_off);
            uint32_t bfrag[4][2];
#pragma unroll
            for (int p = 0; p < 2; p++) {
                uint32_t r4[4];
                ldmatrix_x4(r4, bfrag_addr(bbuf, lane, wn * 32 + p * 16,
                                           ROWB, ks * 32));
                bfrag[2 * p + 0][0] = r4[0]; bfrag[2 * p + 0][1] = r4[1];
                bfrag[2 * p + 1][0] = r4[2]; bfrag[2 * p + 1][1] = r4[3];
            }
#pragma unroll
            for (int mf = 0; mf < 4; mf++)
#pragma unroll
                for (int nf = 0; nf < 4; nf++)
                    mma_fp16(acc[mf][nf], afrag[mf], bfrag[nf]);
        }
        __syncthreads();
    }

    // ---- epilogue ----
    const float CSCL = (float)(0.08838834764831845 * 1.4426950408889634);
    float2 bfr[4];
#pragma unroll
    for (int nf = 0; nf < 4; nf++) {
        int col = bn + wn * 32 + nf * 8 + (lane & 3) * 2;
        bfr[nf].x = __ldg(bias + col);
        bfr[nf].y = __ldg(bias + col + 1);
    }
#pragma unroll
    for (int mf = 0; mf < 4; mf++) {
#pragma unroll
        for (int h8 = 0; h8 < 2; h8++) {
            int row = bm + wm * 64 + mf * 16 + (lane >> 2) + h8 * 8;
#pragma unroll
            for (int nf = 0; nf < 4; nf++) {
                float vx = acc[mf][nf][2 * h8 + 0] + bfr[nf].x;
                float vy = acc[mf][nf][2 * h8 + 1] + bfr[nf].y;
                int coff = wn * 32 + nf * 8 + (lane & 3) * 2;
                if (MODE == 0) {
                    float* C = (float*)outA;
                    float2 o; o.x = vx; o.y = vy;
                    *(float2*)(C + (size_t)row * N + bn + coff) = o;
                } else if (MODE == 1) {
                    __half* dst = (bn < DIM) ? (__half*)outA : (__half*)outB;
                    int cb = (bn & (DIM - 1)) + coff;
                    *(__half2*)(dst + (size_t)row * DIM + cb) =
                        __floats2half2_rn(vx, vy);
                } else {
                    *(__half2*)((__half*)outA + (size_t)row * DIM + bn + coff) =
                        __floats2half2_rn(vx * CSCL, vy * CSCL);
                }
            }
        }
    }
}

// ---------------- fp16 tensor-core flash attention (single Q pass) ----------------
#define SM_QH   0
#define SM_K0   17408
#define SM_K1   34816
#define SM_V    52224
#define SM_P    69632
#define SM_RMAX 78848
#define SM_RSUM 79360
#define ATT_SMEM 79872

__global__ __launch_bounds__(256, 2) void attn_tc_kernel(
    const __half* __restrict__ Qh,
    const __half* __restrict__ K16, const __half* __restrict__ V16,
    __half* __restrict__ OAh, __half* __restrict__ OAl)
{
    extern __shared__ char smem[];
    const uint32_t sb = smem_u32(smem);
    const int tid = threadIdx.x, lane = tid & 31, wid = tid >> 5;
    const int wm = wid & 3, wn = wid >> 2;
    const int qt = (int)gridDim.x - 1 - (int)blockIdx.x;
    const int bh = blockIdx.y, bb = bh >> 4, hh = bh & 15;
    const int q0 = qt * 64;
    const size_t rowbase = (size_t)bb * TSEQ;
    const int hoff = hh * HD;

    float* sRMax = (float*)(smem + SM_RMAX);
    float* sRSum = (float*)(smem + SM_RSUM);

#pragma unroll
    for (int it = 0; it < 4; it++) {
        int idx = tid + it * 256; int r = idx >> 4, sg = idx & 15;
        CP_ASYNC16(sb + SM_QH + r * 272 + sg * 16,
                   Qh + (rowbase + q0 + r) * DIM + hoff + sg * 8);
    }
    asm volatile("cp.async.commit_group;");

    auto loadK = [&](int j0, uint32_t base) {
#pragma unroll
        for (int it = 0; it < 4; it++) {
            int idx = tid + it * 256; int r = idx >> 4, sg = idx & 15;
            CP_ASYNC16(base + r * 272 + sg * 16,
                       K16 + (rowbase + j0 + r) * DIM + hoff + sg * 8);
        }
        asm volatile("cp.async.commit_group;");
    };
    auto loadV = [&](int j0) {
#pragma unroll
        for (int it = 0; it < 4; it++) {
            int idx = tid + it * 256; int r = idx >> 4, sg = idx & 15;
            CP_ASYNC16(sb + SM_V + r * 272 + sg * 16,
                       V16 + (rowbase + j0 + r) * DIM + hoff + sg * 8);
        }
        asm volatile("cp.async.commit_group;");
    };

    loadK(0, sb + SM_K0);

    float oacc[8][4];
#pragma unroll
    for (int i = 0; i < 8; i++)
#pragma unroll
        for (int k = 0; k < 4; k++) oacc[i][k] = 0.f;
    float m0 = -1e9f, m1 = -1e9f, l0 = 0.f, l1 = 0.f;

    const int r0 = wm * 16 + (lane >> 2);
    const int r1 = r0 + 8;
    int buf = 0;

    for (int j = 0; j <= qt; j++) {
        const int j0 = j * 64;
        loadV(j0);
        if (j < qt) loadK(j0 + 64, sb + (buf ? SM_K0 : SM_K1));
        if (j < qt) asm volatile("cp.async.wait_group 2;");
        else        asm volatile("cp.async.wait_group 1;");
        __syncthreads();   // S1

        const uint32_t kb = sb + (buf ? SM_K1 : SM_K0);
        float sacc[4][4];
#pragma unroll
        for (int nf = 0; nf < 4; nf++)
#pragma unroll
            for (int e = 0; e < 4; e++) sacc[nf][e] = 0.f;

#pragma unroll
        for (int kc = 0; kc < 8; kc++) {
            uint32_t bbf[4][2];
#pragma unroll
            for (int p = 0; p < 2; p++) {
                uint32_t r4[4];
                ldmatrix_x4(r4, bfrag_addr(kb, lane, wn * 32 + p * 16,
                                           272, kc * 32));
                bbf[2 * p + 0][0] = r4[0]; bbf[2 * p + 0][1] = r4[1];
                bbf[2 * p + 1][0] = r4[2]; bbf[2 * p + 1][1] = r4[3];
            }
            uint32_t qa = (uint32_t)((wm * 16 + (lane & 15)) * 272
                                     + kc * 32 + (lane >> 4) * 16);
            uint32_t ah[4];
            ldmatrix_x4(ah, sb + SM_QH + qa);
#pragma unroll
            for (int nf = 0; nf < 4; nf++)
                mma_fp16(sacc[nf], ah, bbf[nf]);
        }

        if (j == qt) {
#pragma unroll
            for (int nf = 0; nf < 4; nf++)
#pragma unroll
                for (int e = 0; e < 4; e++) {
                    int col = j0 + wn * 32 + nf * 8 + 2 * (lane & 3) + (e & 1);
                    int row = q0 + ((e >> 1) ? r1 : r0);
                    if (col > row) sacc[nf][e] = -1e9f;
                }
        }

        float mx0 = -1e30f, mx1 = -1e30f;
#pragma unroll
        for (int nf = 0; nf < 4; nf++) {
            mx0 = fmaxf(mx0, fmaxf(sacc[nf][0], sacc[nf][1]));
            mx1 = fmaxf(mx1, fmaxf(sacc[nf][2], sacc[nf][3]));
        }
        mx0 = fmaxf(mx0, __shfl_xor_sync(0xffffffffu, mx0, 1));
        mx0 = fmaxf(mx0, __shfl_xor_sync(0xffffffffu, mx0, 2));
        mx1 = fmaxf(mx1, __shfl_xor_sync(0xffffffffu, mx1, 1));
        mx1 = fmaxf(mx1, __shfl_xor_sync(0xffffffffu, mx1, 2));
        if ((lane & 3) == 0) {
            sRMax[r0 * 2 + wn] = mx0;
            sRMax[r1 * 2 + wn] = mx1;
        }
        __syncthreads();   // S2

        float nm0 = fmaxf(m0, fmaxf(sRMax[r0 * 2], sRMax[r0 * 2 + 1]));
        float nm1 = fmaxf(m1, fmaxf(sRMax[r1 * 2], sRMax[r1 * 2 + 1]));
        float alpha0 = exp2p(m0 - nm0);
        float alpha1 = exp2p(m1 - nm1);
        m0 = nm0; m1 = nm1;

        float s0 = 0.f, s1 = 0.f;
        uint32_t pbase = sb + SM_P + (uint32_t)((wm * 16 + (lane >> 2)) * 144
                                                + wn * 64 + (lane & 3) * 4);
#pragma unroll
        for (int nf = 0; nf < 4; nf++) {
            float p0 = exp2p(sacc[nf][0] - m0);
            float p1 = exp2p(sacc[nf][1] - m0);
            float p2 = exp2p(sacc[nf][2] - m1);
            float p3 = exp2p(sacc[nf][3] - m1);
            s0 += p0 + p1; s1 += p2 + p3;
            __half2 hp0 = __floats2half2_rn(p0, p1);
            __half2 hp1 = __floats2half2_rn(p2, p3);
            sts32(pbase + nf * 16,           *(uint32_t*)&hp0);
            sts32(pbase + nf * 16 + 8 * 144, *(uint32_t*)&hp1);
        }
        s0 += __shfl_xor_sync(0xffffffffu, s0, 1);
        s0 += __shfl_xor_sync(0xffffffffu, s0, 2);
        s1 += __shfl_xor_sync(0xffffffffu, s1, 1);
        s1 += __shfl_xor_sync(0xffffffffu, s1, 2);
        if ((lane & 3) == 0) {
            sRSum[r0 * 2 + wn] = s0;
            sRSum[r1 * 2 + wn] = s1;
        }

#pragma unroll
        for (int nb = 0; nb < 8; nb++) {
            oacc[nb][0] *= alpha0; oacc[nb][1] *= alpha0;
            oacc[nb][2] *= alpha1; oacc[nb][3] *= alpha1;
        }

        if (j < qt) asm volatile("cp.async.wait_group 1;");
        else        asm volatile("cp.async.wait_group 0;");
        __syncthreads();   // S3

        l0 = l0 * alpha0 + sRSum[r0 * 2] + sRSum[r0 * 2 + 1];
        l1 = l1 * alpha1 + sRSum[r1 * 2] + sRSum[r1 * 2 + 1];

#pragma unroll
        for (int kc = 0; kc < 4; kc++) {
            uint32_t pa[4];
            ldmatrix_x4(pa, sb + SM_P + (uint32_t)((wm * 16 + (lane & 15)) * 144
                                                   + kc * 32 + (lane >> 4) * 16));
#pragma unroll
            for (int g = 0; g < 4; g++) {
                uint32_t vb[4];
                ldmatrix_x4_trans(vb, sb + SM_V
                    + (uint32_t)((kc * 16 + (lane & 15)) * 272
                                 + (wn * 64 + g * 16 + (lane >> 4) * 8) * 2));
                mma_fp16(oacc[2 * g + 0], pa, &vb[0]);
                mma_fp16(oacc[2 * g + 1], pa, &vb[2]);
            }
        }
        __syncthreads();   // S4
        buf ^= 1;
    }

    float li0 = 1.f / l0, li1 = 1.f / l1;
    size_t a0 = (rowbase + q0 + r0) * DIM + hoff + wn * 64;
    size_t a1 = (rowbase + q0 + r1) * DIM + hoff + wn * 64;
#pragma unroll
    for (int nb = 0; nb < 8; nb++) {
        int c = nb * 8 + 2 * (lane & 3);
        float o0 = oacc[nb][0] * li0, o1 = oacc[nb][1] * li0;
        float o2 = oacc[nb][2] * li1, o3 = oacc[nb][3] * li1;
        __half h0 = __float2half_rn(o0), h1 = __float2half_rn(o1);
        __half h2 = __float2half_rn(o2), h3 = __float2half_rn(o3);
        *(__half2*)(OAh + a0 + c) = __halves2half2(h0, h1);
        *(__half2*)(OAh + a1 + c) = __halves2half2(h2, h3);
        *(__half2*)(OAl + a0 + c) =
            __floats2half2_rn(o0 - __half2float(h0), o1 - __half2float(h1));
        *(__half2*)(OAl + a1 + c) =
            __floats2half2_rn(o2 - __half2float(h2), o3 - __half2float(h3));
    }
}

// ---------------- launch ----------------
extern "C" void kernel_launch(void* const* d_in, const int* in_sizes, int n_in,
                              void* d_out, int out_size)
{
    const float* enc  = (const float*)d_in[0];
    const float* dec  = (const float*)d_in[1];
    const float* W_kv = (const float*)d_in[2];
    const float* b_kv = (const float*)d_in[3];
    const float* W_q  = (const float*)d_in[4];
    const float* b_q  = (const float*)d_in[5];
    const float* W_o  = (const float*)d_in[6];
    const float* b_o  = (const float*)d_in[7];
    float* out = (float*)d_out;

    __half *p_Ah, *p_Al, *p_Wh, *p_K, *p_V, *p_Qh;
    cudaGetSymbolAddress((void**)&p_Ah, g_Ah);
    cudaGetSymbolAddress((void**)&p_Al, g_Al);
    cudaGetSymbolAddress((void**)&p_Wh, g_Wh);
    cudaGetSymbolAddress((void**)&p_K,  g_K16);
    cudaGetSymbolAddress((void**)&p_V,  g_V16);
    cudaGetSymbolAddress((void**)&p_Qh, g_Qh);

    cudaFuncSetAttribute((const void*)gemm_tc_kernel<0,2>, cudaFuncAttributeMaxDynamicSharedMemorySize, GEMM_SMEM);
    cudaFuncSetAttribute((const void*)gemm_tc_kernel<1,1>, cudaFuncAttributeMaxDynamicSharedMemorySize, GEMM_SMEM);
    cudaFuncSetAttribute((const void*)gemm_tc_kernel<2,1>, cudaFuncAttributeMaxDynamicSharedMemorySize, GEMM_SMEM);
    cudaFuncSetAttribute(attn_tc_kernel, cudaFuncAttributeMaxDynamicSharedMemorySize, ATT_SMEM);

    const int nA4 = MROWS * DIM / 4;

    // GEMM 1: kv projection -> K16/V16 fp16 (single pass)
    conv_w_kernel<<<dim3(KVDIM / 32, DIM / 32), dim3(32, 8)>>>(W_kv, p_Wh, DIM, KVDIM);
    conv_h_kernel<<<(nA4 + 255) / 256, 256>>>(enc, p_Ah, nA4);
    gemm_tc_kernel<1,1><<<dim3(KVDIM / 128, MROWS / 128), 256, GEMM_SMEM>>>(
        p_Ah, nullptr, p_Wh, b_kv, p_K, p_V, KVDIM);

    // GEMM 2: q projection -> scaled fp16 Qh (single pass)
    conv_w_kernel<<<dim3(DIM / 32, DIM / 32), dim3(32, 8)>>>(W_q, p_Wh, DIM, DIM);
    conv_h_kernel<<<(nA4 + 255) / 256, 256>>>(dec, p_Ah, nA4);
    gemm_tc_kernel<2,1><<<dim3(DIM / 128, MROWS / 128), 256, GEMM_SMEM>>>(
        p_Ah, nullptr, p_Wh, b_q, p_Qh, nullptr, DIM);

    // attention -> split fp16 into Ah/Al
    attn_tc_kernel<<<dim3(TSEQ / 64, BATCH * NHEAD), 256, ATT_SMEM>>>(
        p_Qh, p_K, p_V, p_Ah, p_Al);

    // GEMM 3: output projection (fp32 out, 2-pass for accuracy)
    conv_w_kernel<<<dim3(DIM / 32, DIM / 32), dim3(32, 8)>>>(W_o, p_Wh, DIM, DIM);
    gemm_tc_kernel<0,2><<<dim3(DIM / 128, MROWS / 128), 256, GEMM_SMEM>>>(
        p_Ah, p_Al, p_Wh, b_o, out, nullptr, DIM);
}

// round 11
// speedup vs baseline: 7.6138x; 1.1856x over previous
#include <cuda_runtime.h>
#include <cuda_fp16.h>
#include <cstdint>

#define TSEQ   2048
#define BATCH  4
#define NHEAD  16
#define HD     128
#define DIM    2048
#define MROWS  (BATCH * TSEQ)   // 8192
#define KVDIM  (2 * DIM)        // 4096

// ---------------- scratch (allocation-free: __device__ globals) ----------------
__device__ __half g_Ah [(size_t)MROWS * DIM];
__device__ __half g_Wh [(size_t)KVDIM * DIM];   // fp16 W, native [K,N] layout
__device__ __half g_K16[(size_t)MROWS * DIM];
__device__ __half g_V16[(size_t)MROWS * DIM];
__device__ __half g_Qh [(size_t)MROWS * DIM];

// ---------------- helpers ----------------
__device__ __forceinline__ uint32_t smem_u32(const void* p) {
    uint32_t a;
    asm("{ .reg .u64 t; cvta.to.shared.u64 t, %1; cvt.u32.u64 %0, t; }"
        : "=r"(a) : "l"(p));
    return a;
}
#define CP_ASYNC16(dst, src) \
    asm volatile("cp.async.cg.shared.global [%0], [%1], 16;" :: "r"(dst), "l"(src))

__device__ __forceinline__ void ldmatrix_x4(uint32_t* r, uint32_t addr) {
    asm volatile("ldmatrix.sync.aligned.m8n8.x4.shared.b16 {%0,%1,%2,%3}, [%4];"
                 : "=r"(r[0]), "=r"(r[1]), "=r"(r[2]), "=r"(r[3]) : "r"(addr));
}
__device__ __forceinline__ void ldmatrix_x4_trans(uint32_t* r, uint32_t addr) {
    asm volatile("ldmatrix.sync.aligned.m8n8.x4.trans.shared.b16 {%0,%1,%2,%3}, [%4];"
                 : "=r"(r[0]), "=r"(r[1]), "=r"(r[2]), "=r"(r[3]) : "r"(addr));
}
__device__ __forceinline__ void sts32(uint32_t a, uint32_t v) {
    asm volatile("st.shared.b32 [%0], %1;" :: "r"(a), "r"(v));
}
__device__ __forceinline__ void mma_fp16(float* d, const uint32_t* a, const uint32_t* b) {
    asm volatile(
        "mma.sync.aligned.m16n8k16.row.col.f32.f16.f16.f32 "
        "{%0,%1,%2,%3}, {%4,%5,%6,%7}, {%8,%9}, {%0,%1,%2,%3};"
        : "+f"(d[0]), "+f"(d[1]), "+f"(d[2]), "+f"(d[3])
        : "r"(a[0]), "r"(a[1]), "r"(a[2]), "r"(a[3]), "r"(b[0]), "r"(b[1]));
}

// fast exp2 on FMA pipe (t <= ~0)
__device__ __forceinline__ float exp2p(float t) {
    t = fmaxf(t, -126.f);
    float fi = floorf(t);
    float x = t - fi - 0.5f;
    float p = 0.001885630f;
    p = fmaf(p, x, 0.013602145f);
    p = fmaf(p, x, 0.078494717f);
    p = fmaf(p, x, 0.339731669f);
    p = fmaf(p, x, 0.980258143f);
    p = fmaf(p, x, 1.414213562f);
    int e = (int)fi;
    return __int_as_float(__float_as_int(p) + (e << 23));
}

// ---------------- conversion kernel (elementwise fp32 -> fp16) ----------------
__global__ __launch_bounds__(256) void conv_h_kernel(
    const float* __restrict__ x, __half* __restrict__ h, int n4)
{
    int i = blockIdx.x * 256 + threadIdx.x;
    if (i >= n4) return;
    float4 v = ((const float4*)x)[i];
    __half2* hp = (__half2*)(h + (size_t)i * 4);
    hp[0] = __floats2half2_rn(v.x, v.y);
    hp[1] = __floats2half2_rn(v.z, v.w);
}

// ---------------- mma.sync GEMM (fp16, single pass), templated epilogue ----------------
// A: fp16 [M, 2048] row-major. W: fp16 [K, N] native layout (B frags via ldmatrix.trans).
// MODE 0: fp32 C = acc + bias           (outA = float* C)
// MODE 1: fp16 K/V split by column      (outA = K16, outB = V16)
// MODE 2: fp16 scaled q                 (outA = Qh)
#define BKG      64
#define ROWB     144                       // A smem row stride (72 halfs)
#define BROWB    272                       // B smem row stride (136 halfs, k-rows of 128 n)
#define ATILE_B  (128 * ROWB)              // 18432
#define BTILE_B  (64 * BROWB)              // 17408
#define BUF_B    (ATILE_B + BTILE_B)       // 35840
#define GEMM_SMEM (2 * BUF_B)              // 71680 -> 2 CTAs/SM
#define NCH 32

template<int MODE>
__global__ __launch_bounds__(256, 2) void gemm_tc_kernel(
    const __half* __restrict__ Ah, const __half* __restrict__ Wf,
    const float* __restrict__ bias, void* outA, void* outB, int N)
{
    extern __shared__ char smem[];
    const uint32_t sbase = smem_u32(smem);
    const int tid  = threadIdx.x;
    const int wid  = tid >> 5;
    const int lane = tid & 31;
    const int wm   = wid & 1;
    const int wn   = wid >> 1;
    const int bm   = blockIdx.y * 128;
    const int bn   = blockIdx.x * 128;

    float acc[4][4][4];
#pragma unroll
    for (int i = 0; i < 4; i++)
#pragma unroll
        for (int j = 0; j < 4; j++)
#pragma unroll
            for (int k = 0; k < 4; k++) acc[i][j][k] = 0.f;

    const uint32_t a_lane_off = (uint32_t)((lane & 15) * ROWB + ((lane >> 4) << 3) * 2);
    const uint32_t a_warp_base = (uint32_t)(wm * 64) * ROWB;

    auto load_chunk = [&](int ci, int buf) {
        const int k0 = ci * BKG;
        const uint32_t base = sbase + (uint32_t)buf * BUF_B;
#pragma unroll
        for (int j = 0; j < 8; j++) {
            int c = j * 256 + tid;
            uint32_t dst;
            const __half* g;
            if (c < 1024) {               // A tile: 128 rows x 64 k
                int row = c >> 3, seg = c & 7;
                dst = base + (uint32_t)(row * ROWB + seg * 16);
                g = Ah + (size_t)(bm + row) * DIM + k0 + seg * 8;
            } else {                      // B tile: 64 k-rows x 128 n
                int idx = c - 1024;
                int row = idx >> 4, seg = idx & 15;
                dst = base + (uint32_t)(ATILE_B + row * BROWB + seg * 16);
                g = Wf + (size_t)(k0 + row) * N + bn + seg * 8;
            }
            CP_ASYNC16(dst, g);
        }
        asm volatile("cp.async.commit_group;");
    };

    load_chunk(0, 0);

    for (int i = 0; i < NCH; i++) {
        const int b = i & 1;
        const bool has_next = (i + 1 < NCH);
        if (has_next) load_chunk(i + 1, b ^ 1);
        if (has_next) asm volatile("cp.async.wait_group 1;");
        else          asm volatile("cp.async.wait_group 0;");
        __syncthreads();

        const uint32_t abuf = sbase + (uint32_t)b * BUF_B;
        const uint32_t bbuf = abuf + ATILE_B;
#pragma unroll
        for (int ks = 0; ks < 4; ks++) {
            uint32_t afrag[4][4];
#pragma unroll
            for (int mf = 0; mf < 4; mf++)
                ldmatrix_x4(afrag[mf],
                            abuf + a_warp_base + (uint32_t)(mf * 16 * ROWB)
                                 + (uint32_t)(ks * 32) + a_lane_off);
            uint32_t bfrag[4][2];
#pragma unroll
            for (int p = 0; p < 2; p++) {
                uint32_t r4[4];
                ldmatrix_x4_trans(r4, bbuf
                    + (uint32_t)((ks * 16 + (lane & 15)) * BROWB
                                 + (wn * 32 + p * 16 + (lane >> 4) * 8) * 2));
                bfrag[2 * p + 0][0] = r4[0]; bfrag[2 * p + 0][1] = r4[1];
                bfrag[2 * p + 1][0] = r4[2]; bfrag[2 * p + 1][1] = r4[3];
            }
#pragma unroll
            for (int mf = 0; mf < 4; mf++)
#pragma unroll
                for (int nf = 0; nf < 4; nf++)
                    mma_fp16(acc[mf][nf], afrag[mf], bfrag[nf]);
        }
        __syncthreads();
    }

    // ---- epilogue ----
    const float CSCL = (float)(0.08838834764831845 * 1.4426950408889634);
    float2 bfr[4];
#pragma unroll
    for (int nf = 0; nf < 4; nf++) {
        int col = bn + wn * 32 + nf * 8 + (lane & 3) * 2;
        bfr[nf].x = __ldg(bias + col);
        bfr[nf].y = __ldg(bias + col + 1);
    }
#pragma unroll
    for (int mf = 0; mf < 4; mf++) {
#pragma unroll
        for (int h8 = 0; h8 < 2; h8++) {
            int row = bm + wm * 64 + mf * 16 + (lane >> 2) + h8 * 8;
#pragma unroll
            for (int nf = 0; nf < 4; nf++) {
                float vx = acc[mf][nf][2 * h8 + 0] + bfr[nf].x;
                float vy = acc[mf][nf][2 * h8 + 1] + bfr[nf].y;
                int coff = wn * 32 + nf * 8 + (lane & 3) * 2;
                if (MODE == 0) {
                    float* C = (float*)outA;
                    float2 o; o.x = vx; o.y = vy;
                    *(float2*)(C + (size_t)row * N + bn + coff) = o;
                } else if (MODE == 1) {
                    __half* dst = (bn < DIM) ? (__half*)outA : (__half*)outB;
                    int cb = (bn & (DIM - 1)) + coff;
                    *(__half2*)(dst + (size_t)row * DIM + cb) =
                        __floats2half2_rn(vx, vy);
                } else {
                    *(__half2*)((__half*)outA + (size_t)row * DIM + bn + coff) =
                        __floats2half2_rn(vx * CSCL, vy * CSCL);
                }
            }
        }
    }
}

// ---------------- fp16 tensor-core flash attention (single Q pass) ----------------
#define SM_QH   0
#define SM_K0   17408
#define SM_K1   34816
#define SM_V    52224
#define SM_P    69632
#define SM_RMAX 78848
#define SM_RSUM 79360
#define ATT_SMEM 79872

__global__ __launch_bounds__(256, 2) void attn_tc_kernel(
    const __half* __restrict__ Qh,
    const __half* __restrict__ K16, const __half* __restrict__ V16,
    __half* __restrict__ OAh)
{
    extern __shared__ char smem[];
    const uint32_t sb = smem_u32(smem);
    const int tid = threadIdx.x, lane = tid & 31, wid = tid >> 5;
    const int wm = wid & 3, wn = wid >> 2;
    const int qt = (int)gridDim.x - 1 - (int)blockIdx.x;
    const int bh = blockIdx.y, bb = bh >> 4, hh = bh & 15;
    const int q0 = qt * 64;
    const size_t rowbase = (size_t)bb * TSEQ;
    const int hoff = hh * HD;

    float* sRMax = (float*)(smem + SM_RMAX);
    float* sRSum = (float*)(smem + SM_RSUM);

#pragma unroll
    for (int it = 0; it < 4; it++) {
        int idx = tid + it * 256; int r = idx >> 4, sg = idx & 15;
        CP_ASYNC16(sb + SM_QH + r * 272 + sg * 16,
                   Qh + (rowbase + q0 + r) * DIM + hoff + sg * 8);
    }
    asm volatile("cp.async.commit_group;");

    auto loadK = [&](int j0, uint32_t base) {
#pragma unroll
        for (int it = 0; it < 4; it++) {
            int idx = tid + it * 256; int r = idx >> 4, sg = idx & 15;
            CP_ASYNC16(base + r * 272 + sg * 16,
                       K16 + (rowbase + j0 + r) * DIM + hoff + sg * 8);
        }
        asm volatile("cp.async.commit_group;");
    };
    auto loadV = [&](int j0) {
#pragma unroll
        for (int it = 0; it < 4; it++) {
            int idx = tid + it * 256; int r = idx >> 4, sg = idx & 15;
            CP_ASYNC16(sb + SM_V + r * 272 + sg * 16,
                       V16 + (rowbase + j0 + r) * DIM + hoff + sg * 8);
        }
        asm volatile("cp.async.commit_group;");
    };

    loadK(0, sb + SM_K0);

    float oacc[8][4];
#pragma unroll
    for (int i = 0; i < 8; i++)
#pragma unroll
        for (int k = 0; k < 4; k++) oacc[i][k] = 0.f;
    float m0 = -1e9f, m1 = -1e9f, l0 = 0.f, l1 = 0.f;

    const int r0 = wm * 16 + (lane >> 2);
    const int r1 = r0 + 8;
    int buf = 0;

    for (int j = 0; j <= qt; j++) {
        const int j0 = j * 64;
        loadV(j0);
        if (j < qt) loadK(j0 + 64, sb + (buf ? SM_K0 : SM_K1));
        if (j < qt) asm volatile("cp.async.wait_group 2;");
        else        asm volatile("cp.async.wait_group 1;");
        __syncthreads();   // S1

        const uint32_t kb = sb + (buf ? SM_K1 : SM_K0);
        float sacc[4][4];
#pragma unroll
        for (int nf = 0; nf < 4; nf++)
#pragma unroll
            for (int e = 0; e < 4; e++) sacc[nf][e] = 0.f;

#pragma unroll
        for (int kc = 0; kc < 8; kc++) {
            uint32_t bbf[4][2];
#pragma unroll
            for (int p = 0; p < 2; p++) {
                uint32_t r4[4];
                int g = lane >> 3, r = lane & 7;
                ldmatrix_x4(r4, kb + (uint32_t)(
                    (wn * 32 + p * 16 + ((g >> 1) << 3) + r) * 272
                    + kc * 32 + ((g & 1) << 4)));
                bbf[2 * p + 0][0] = r4[0]; bbf[2 * p + 0][1] = r4[1];
                bbf[2 * p + 1][0] = r4[2]; bbf[2 * p + 1][1] = r4[3];
            }
            uint32_t qa = (uint32_t)((wm * 16 + (lane & 15)) * 272
                                     + kc * 32 + (lane >> 4) * 16);
            uint32_t ah[4];
            ldmatrix_x4(ah, sb + SM_QH + qa);
#pragma unroll
            for (int nf = 0; nf < 4; nf++)
                mma_fp16(sacc[nf], ah, bbf[nf]);
        }

        if (j == qt) {
#pragma unroll
            for (int nf = 0; nf < 4; nf++)
#pragma unroll
                for (int e = 0; e < 4; e++) {
                    int col = j0 + wn * 32 + nf * 8 + 2 * (lane & 3) + (e & 1);
                    int row = q0 + ((e >> 1) ? r1 : r0);
                    if (col > row) sacc[nf][e] = -1e9f;
                }
        }

        float mx0 = -1e30f, mx1 = -1e30f;
#pragma unroll
        for (int nf = 0; nf < 4; nf++) {
            mx0 = fmaxf(mx0, fmaxf(sacc[nf][0], sacc[nf][1]));
            mx1 = fmaxf(mx1, fmaxf(sacc[nf][2], sacc[nf][3]));
        }
        mx0 = fmaxf(mx0, __shfl_xor_sync(0xffffffffu, mx0, 1));
        mx0 = fmaxf(mx0, __shfl_xor_sync(0xffffffffu, mx0, 2));
        mx1 = fmaxf(mx1, __shfl_xor_sync(0xffffffffu, mx1, 1));
        mx1 = fmaxf(mx1, __shfl_xor_sync(0xffffffffu, mx1, 2));
        if ((lane & 3) == 0) {
            sRMax[r0 * 2 + wn] = mx0;
            sRMax[r1 * 2 + wn] = mx1;
        }
        __syncthreads();   // S2

        float nm0 = fmaxf(m0, fmaxf(sRMax[r0 * 2], sRMax[r0 * 2 + 1]));
        float nm1 = fmaxf(m1, fmaxf(sRMax[r1 * 2], sRMax[r1 * 2 + 1]));
        float alpha0 = exp2p(m0 - nm0);
        float alpha1 = exp2p(m1 - nm1);
        m0 = nm0; m1 = nm1;

        float s0 = 0.f, s1 = 0.f;
        uint32_t pbase = sb + SM_P + (uint32_t)((wm * 16 + (lane >> 2)) * 144
                                                + wn * 64 + (lane & 3) * 4);
#pragma unroll
        for (int nf = 0; nf < 4; nf++) {
            float p0 = exp2p(sacc[nf][0] - m0);
            float p1 = exp2p(sacc[nf][1] - m0);
            float p2 = exp2p(sacc[nf][2] - m1);
            float p3 = exp2p(sacc[nf][3] - m1);
            s0 += p0 + p1; s1 += p2 + p3;
            __half2 hp0 = __floats2half2_rn(p0, p1);
            __half2 hp1 = __floats2half2_rn(p2, p3);
            sts32(pbase + nf * 16,           *(uint32_t*)&hp0);
            sts32(pbase + nf * 16 + 8 * 144, *(uint32_t*)&hp1);
        }
        s0 += __shfl_xor_sync(0xffffffffu, s0, 1);
        s0 += __shfl_xor_sync(0xffffffffu, s0, 2);
        s1 += __shfl_xor_sync(0xffffffffu, s1, 1);
        s1 += __shfl_xor_sync(0xffffffffu, s1, 2);
        if ((lane & 3) == 0) {
            sRSum[r0 * 2 + wn] = s0;
            sRSum[r1 * 2 + wn] = s1;
        }

#pragma unroll
        for (int nb = 0; nb < 8; nb++) {
            oacc[nb][0] *= alpha0; oacc[nb][1] *= alpha0;
            oacc[nb][2] *= alpha1; oacc[nb][3] *= alpha1;
        }

        if (j < qt) asm volatile("cp.async.wait_group 1;");
        else        asm volatile("cp.async.wait_group 0;");
        __syncthreads();   // S3

        l0 = l0 * alpha0 + sRSum[r0 * 2] + sRSum[r0 * 2 + 1];
        l1 = l1 * alpha1 + sRSum[r1 * 2] + sRSum[r1 * 2 + 1];

#pragma unroll
        for (int kc = 0; kc < 4; kc++) {
            uint32_t pa[4];
            ldmatrix_x4(pa, sb + SM_P + (uint32_t)((wm * 16 + (lane & 15)) * 144
                                                   + kc * 32 + (lane >> 4) * 16));
#pragma unroll
            for (int g = 0; g < 4; g++) {
                uint32_t vb[4];
                ldmatrix_x4_trans(vb, sb + SM_V
                    + (uint32_t)((kc * 16 + (lane & 15)) * 272
                                 + (wn * 64 + g * 16 + (lane >> 4) * 8) * 2));
                mma_fp16(oacc[2 * g + 0], pa, &vb[0]);
                mma_fp16(oacc[2 * g + 1], pa, &vb[2]);
            }
        }
        __syncthreads();   // S4
        buf ^= 1;
    }

    float li0 = 1.f / l0, li1 = 1.f / l1;
    size_t a0 = (rowbase + q0 + r0) * DIM + hoff + wn * 64;
    size_t a1 = (rowbase + q0 + r1) * DIM + hoff + wn * 64;
#pragma unroll
    for (int nb = 0; nb < 8; nb++) {
        int c = nb * 8 + 2 * (lane & 3);
        *(__half2*)(OAh + a0 + c) =
            __floats2half2_rn(oacc[nb][0] * li0, oacc[nb][1] * li0);
        *(__half2*)(OAh + a1 + c) =
            __floats2half2_rn(oacc[nb][2] * li1, oacc[nb][3] * li1);
    }
}

// ---------------- launch ----------------
extern "C" void kernel_launch(void* const* d_in, const int* in_sizes, int n_in,
                              void* d_out, int out_size)
{
    const float* enc  = (const float*)d_in[0];
    const float* dec  = (const float*)d_in[1];
    const float* W_kv = (const float*)d_in[2];
    const float* b_kv = (const float*)d_in[3];
    const float* W_q  = (const float*)d_in[4];
    const float* b_q  = (const float*)d_in[5];
    const float* W_o  = (const float*)d_in[6];
    const float* b_o  = (const float*)d_in[7];
    float* out = (float*)d_out;

    __half *p_Ah, *p_Wh, *p_K, *p_V, *p_Qh;
    cudaGetSymbolAddress((void**)&p_Ah, g_Ah);
    cudaGetSymbolAddress((void**)&p_Wh, g_Wh);
    cudaGetSymbolAddress((void**)&p_K,  g_K16);
    cudaGetSymbolAddress((void**)&p_V,  g_V16);
    cudaGetSymbolAddress((void**)&p_Qh, g_Qh);

    cudaFuncSetAttribute((const void*)gemm_tc_kernel<0>, cudaFuncAttributeMaxDynamicSharedMemorySize, GEMM_SMEM);
    cudaFuncSetAttribute((const void*)gemm_tc_kernel<1>, cudaFuncAttributeMaxDynamicSharedMemorySize, GEMM_SMEM);
    cudaFuncSetAttribute((const void*)gemm_tc_kernel<2>, cudaFuncAttributeMaxDynamicSharedMemorySize, GEMM_SMEM);
    cudaFuncSetAttribute(attn_tc_kernel, cudaFuncAttributeMaxDynamicSharedMemorySize, ATT_SMEM);

    const int nA4 = MROWS * DIM / 4;

    // GEMM 1: kv projection -> K16/V16 fp16
    conv_h_kernel<<<(DIM * KVDIM / 4 + 255) / 256, 256>>>(W_kv, p_Wh, DIM * KVDIM / 4);
    conv_h_kernel<<<(nA4 + 255) / 256, 256>>>(enc, p_Ah, nA4);
    gemm_tc_kernel<1><<<dim3(KVDIM / 128, MROWS / 128), 256, GEMM_SMEM>>>(
        p_Ah, p_Wh, b_kv, p_K, p_V, KVDIM);

    // GEMM 2: q projection -> scaled fp16 Qh
    conv_h_kernel<<<(DIM * DIM / 4 + 255) / 256, 256>>>(W_q, p_Wh, DIM * DIM / 4);
    conv_h_kernel<<<(nA4 + 255) / 256, 256>>>(dec, p_Ah, nA4);
    gemm_tc_kernel<2><<<dim3(DIM / 128, MROWS / 128), 256, GEMM_SMEM>>>(
        p_Ah, p_Wh, b_q, p_Qh, nullptr, DIM);

    // attention -> fp16 AO into Ah (GEMM3 input)
    attn_tc_kernel<<<dim3(TSEQ / 64, BATCH * NHEAD), 256, ATT_SMEM>>>(
        p_Qh, p_K, p_V, p_Ah);

    // GEMM 3: output projection (fp32 out)
    conv_h_kernel<<<(DIM * DIM / 4 + 255) / 256, 256>>>(W_o, p_Wh, DIM * DIM / 4);
    gemm_tc_kernel<0><<<dim3(DIM / 128, MROWS / 128), 256, GEMM_SMEM>>>(
        p_Ah, p_Wh, b_o, out, nullptr, DIM);
}